// round 7
// baseline (speedup 1.0000x reference)
#include <cuda_runtime.h>

// Problem constants
#define BSZ 32768
#define HD  128
#define G4  512
#define TIN 20
#define TDEC 45
#define NIN 2
#define NOUT 2

// Tiling
#define MB 32            // batch rows per CTA
#define NTHREADS 512
#define KC 32            // k-chunk
#define P0 132           // padded row stride for h0 state (mult of 4, stride%32=4)
#define P1 260           // padded row stride for [y0|h1] state

typedef unsigned long long ull;

struct Smem {
    float wch[2][KC][G4];        // double-buffered transposed weight chunk (XOR-swizzled cols)
    float h0s[MB * P0];          // layer0 h state
    float xh1[MB * P1];          // [ y0 (0..127) | h1 (128..255) ]
    float xin[MB * (TIN * NIN)]; // encoder inputs staged once
    float be0[G4], be1[G4], bd0[G4], bd1[G4];
    float wieT[2][G4], widT[2][G4];   // input weights transposed for packed loads
    float fcw[NOUT][HD];
    float fcb[NOUT];
    float xdec[MB][NOUT];
};

__device__ __forceinline__ ull pack2(float x) {
    ull r; asm("mov.b64 %0, {%1, %1};" : "=l"(r) : "f"(x)); return r;
}
__device__ __forceinline__ float2 unpk(ull v) {
    float lo, hi; asm("mov.b64 {%0, %1}, %2;" : "=f"(lo), "=f"(hi) : "l"(v));
    return make_float2(lo, hi);
}
#define FMA2(d, a, b) asm("fma.rn.f32x2 %0, %1, %2, %0;" : "+l"(d) : "l"(a), "l"(b))

__device__ __forceinline__ float sigf(float x) {
    return __fdividef(1.0f, 1.0f + __expf(-x));
}
__device__ __forceinline__ float tanhf_(float x) {
    return 2.0f * __fdividef(1.0f, 1.0f + __expf(-2.0f * x)) - 1.0f;
}

// ---- weight staging: coalesced LDG (32 rows x 128B per warp) ----
__device__ __forceinline__ void stage_ldg(float4 stg[8], const float* __restrict__ W,
                                          int w, int l) {
    const int b = l & 7, r = l >> 3;
    #pragma unroll
    for (int i = 0; i < 8; i++)
        stg[i] = *(const float4*)(W + ((w << 5) + (i << 2) + r) * HD + (b << 2));
}
// transpose-store with XOR swizzle: wch[kk][col ^ (kk & 28)], kk = 4b+c
// STS banks: (l>>3) ^ (b<<2) -> 32 distinct -> conflict-free
__device__ __forceinline__ void stage_sts(float* buf, const float4 stg[8], int w, int l) {
    const int b = l & 7, r = l >> 3;
    float* d0 = buf + (b << 2) * G4;
    #pragma unroll
    for (int i = 0; i < 8; i++) {
        const int col = (((w << 5) + (i << 2) + r)) ^ (b << 2);
        d0[col]          = stg[i].x;
        d0[col + G4]     = stg[i].y;
        d0[col + 2 * G4] = stg[i].z;
        d0[col + 3 * G4] = stg[i].w;
    }
}

// gates += st[m][:] . W^T, packed-f32x2 over j pairs.
// W0 covers k in [0,128), W1 covers [128,256).
template <int KTOT, int P>
__device__ __forceinline__ void matmul(ull acc[4][2][2], const float* __restrict__ st,
                                       const float* __restrict__ W0,
                                       const float* __restrict__ W1,
                                       Smem* s, int w, int l, int m0, int j0)
{
    const int NCH = KTOT / KC;
    {   // stage chunk 0 into buffer 0
        float4 stg[8];
        stage_ldg(stg, W0, w, l);
        stage_sts(&s->wch[0][0][0], stg, w, l);
    }
    __syncthreads();
    #pragma unroll 1
    for (int c = 0; c < NCH; c++) {
        float4 stg[8];
        const bool more = (c + 1 < NCH);
        if (more) {
            const int kn = (c + 1) * KC;
            const float* W = (kn < HD) ? (W0 + kn) : (W1 + (kn - HD));
            stage_ldg(stg, W, w, l);           // issue early; latency hidden by compute
        }
        const float* wb  = &s->wch[c & 1][0][0];
        const float* hp0 = st + m0 * P + c * KC;
        const float* hp1 = hp0 + P;
        #pragma unroll 2
        for (int k4 = 0; k4 < KC; k4 += 4) {
            const float4 hA = *(const float4*)(hp0 + k4);
            const float4 hB = *(const float4*)(hp1 + k4);
            #pragma unroll
            for (int u = 0; u < 4; u++) {
                const int kk = k4 + u;
                const ull ha = pack2(((const float*)&hA)[u]);
                const ull hb = pack2(((const float*)&hB)[u]);
                const float* wr = wb + kk * G4;
                const int xk = kk & 28;
                #pragma unroll
                for (int g = 0; g < 4; g++) {
                    const ulonglong2 wv =
                        *(const ulonglong2*)(wr + ((g * HD + j0) ^ xk));
                    FMA2(acc[g][0][0], wv.x, ha);
                    FMA2(acc[g][0][1], wv.x, hb);
                    FMA2(acc[g][1][0], wv.y, ha);
                    FMA2(acc[g][1][1], wv.y, hb);
                }
            }
        }
        if (more) stage_sts(&s->wch[(c + 1) & 1][0][0], stg, w, l);
        __syncthreads();
    }
}

__device__ __forceinline__ void init_bias(ull acc[4][2][2], const float* bias, int j0) {
    #pragma unroll
    for (int g = 0; g < 4; g++)
        #pragma unroll
        for (int jp = 0; jp < 2; jp++) {
            const ull bv = *(const ull*)(bias + g * HD + j0 + jp * 2);
            acc[g][jp][0] = bv;
            acc[g][jp][1] = bv;
        }
}

__device__ __forceinline__ void add_xterm(ull acc[4][2][2], const float (*wT)[G4],
                                          float xA0, float xA1, float xB0, float xB1,
                                          int j0) {
    const ull a0 = pack2(xA0), a1 = pack2(xA1);
    const ull b0 = pack2(xB0), b1 = pack2(xB1);
    #pragma unroll
    for (int g = 0; g < 4; g++)
        #pragma unroll
        for (int jp = 0; jp < 2; jp++) {
            const ull w0 = *(const ull*)(&wT[0][g * HD + j0 + jp * 2]);
            const ull w1 = *(const ull*)(&wT[1][g * HD + j0 + jp * 2]);
            FMA2(acc[g][jp][0], w0, a0);
            FMA2(acc[g][jp][0], w1, a1);
            FMA2(acc[g][jp][1], w0, b0);
            FMA2(acc[g][jp][1], w1, b1);
        }
}

template <bool DUAL>
__device__ __forceinline__ void epilogue(ull acc[4][2][2], float cst[2][4],
                                         float* dst0, int p0, float* dst1, int p1,
                                         int m0, int j0) {
    #pragma unroll
    for (int mi = 0; mi < 2; mi++)
        #pragma unroll
        for (int jp = 0; jp < 2; jp++) {
            const float2 ai = unpk(acc[0][jp][mi]);
            const float2 af = unpk(acc[1][jp][mi]);
            const float2 ag = unpk(acc[2][jp][mi]);
            const float2 ao = unpk(acc[3][jp][mi]);
            #pragma unroll
            for (int q = 0; q < 2; q++) {
                const float xi = q ? ai.y : ai.x;
                const float xf = q ? af.y : af.x;
                const float xg = q ? ag.y : ag.x;
                const float xo = q ? ao.y : ao.x;
                float cn = fmaf(sigf(xf), cst[mi][jp * 2 + q], sigf(xi) * tanhf_(xg));
                cst[mi][jp * 2 + q] = cn;
                const float h = sigf(xo) * tanhf_(cn);
                dst0[(m0 + mi) * p0 + j0 + jp * 2 + q] = h;
                if (DUAL) dst1[(m0 + mi) * p1 + j0 + jp * 2 + q] = h;
            }
        }
}

__global__ void __launch_bounds__(NTHREADS, 1)
trajectory_lstm_kernel(const float* __restrict__ inseq,
                       const float* __restrict__ eWih0, const float* __restrict__ eWhh0,
                       const float* __restrict__ ebih0, const float* __restrict__ ebhh0,
                       const float* __restrict__ eWih1, const float* __restrict__ eWhh1,
                       const float* __restrict__ ebih1, const float* __restrict__ ebhh1,
                       const float* __restrict__ dWih0, const float* __restrict__ dWhh0,
                       const float* __restrict__ dbih0, const float* __restrict__ dbhh0,
                       const float* __restrict__ dWih1, const float* __restrict__ dWhh1,
                       const float* __restrict__ dbih1, const float* __restrict__ dbhh1,
                       const float* __restrict__ fcW, const float* __restrict__ fcb,
                       float* __restrict__ out)
{
    extern __shared__ char raw[];
    Smem* s = (Smem*)raw;

    const int tid = threadIdx.x;
    const int w = tid >> 5, l = tid & 31;
    const int wj = w & 3, wm = w >> 2;
    const int jl = l >> 2, ml = l & 3;
    const int j0 = wj * 32 + jl * 4;    // 4 consecutive j-columns per thread
    const int m0 = wm * 8 + ml * 2;     // 2 consecutive m-rows per thread
    const int bm = blockIdx.x * MB;

    // ---- one-time init ----
    {
        const int g = tid;  // NTHREADS == G4
        s->be0[g] = ebih0[g] + ebhh0[g];
        s->be1[g] = ebih1[g] + ebhh1[g];
        s->bd0[g] = dbih0[g] + dbhh0[g];
        s->bd1[g] = dbih1[g] + dbhh1[g];
        s->wieT[0][g] = eWih0[g * 2];
        s->wieT[1][g] = eWih0[g * 2 + 1];
        s->widT[0][g] = dWih0[g * 2];
        s->widT[1][g] = dWih0[g * 2 + 1];
    }
    if (tid < NOUT * HD) ((float*)s->fcw)[tid] = fcW[tid];
    if (tid < NOUT)      s->fcb[tid] = fcb[tid];
    for (int i = tid; i < MB * P0; i += NTHREADS) s->h0s[i] = 0.0f;
    for (int i = tid; i < MB * P1; i += NTHREADS) s->xh1[i] = 0.0f;
    for (int i = tid; i < MB * TIN * NIN; i += NTHREADS)
        s->xin[i] = inseq[(size_t)bm * (TIN * NIN) + i];
    if (tid < MB * NOUT) {
        const int m = tid >> 1, c = tid & 1;
        s->xdec[m][c] = inseq[(size_t)(bm + m) * (TIN * NIN) + (TIN - 1) * NIN + c];
    }
    __syncthreads();

    float c0[2][4] = {}, c1[2][4] = {};
    ull acc[4][2][2];

    // ================= ENCODER =================
    for (int t = 0; t < TIN; t++) {
        init_bias(acc, s->be0, j0);
        add_xterm(acc, s->wieT,
                  s->xin[m0 * (TIN * NIN) + 2 * t], s->xin[m0 * (TIN * NIN) + 2 * t + 1],
                  s->xin[(m0 + 1) * (TIN * NIN) + 2 * t],
                  s->xin[(m0 + 1) * (TIN * NIN) + 2 * t + 1], j0);
        matmul<HD, P0>(acc, s->h0s, eWhh0, eWhh0, s, w, l, m0, j0);
        epilogue<true>(acc, c0, s->h0s, P0, s->xh1, P1, m0, j0);

        init_bias(acc, s->be1, j0);
        matmul<2 * HD, P1>(acc, s->xh1, eWih1, eWhh1, s, w, l, m0, j0);
        epilogue<false>(acc, c1, s->xh1 + HD, P1, nullptr, 0, m0, j0);
    }

    // ================= DECODER =================
    for (int t = 0; t < TDEC; t++) {
        init_bias(acc, s->bd0, j0);
        add_xterm(acc, s->widT,
                  s->xdec[m0][0], s->xdec[m0][1],
                  s->xdec[m0 + 1][0], s->xdec[m0 + 1][1], j0);
        matmul<HD, P0>(acc, s->h0s, dWhh0, dWhh0, s, w, l, m0, j0);
        epilogue<true>(acc, c0, s->h0s, P0, s->xh1, P1, m0, j0);

        init_bias(acc, s->bd1, j0);
        matmul<2 * HD, P1>(acc, s->xh1, dWih1, dWhh1, s, w, l, m0, j0);
        epilogue<false>(acc, c1, s->xh1 + HD, P1, nullptr, 0, m0, j0);
        __syncthreads();   // h1 complete before fc reads it

        // fc head: pred = h1 @ fcW^T + fcb (parallel dot, 8-lane tree reduce)
        {
            const int m = tid >> 4, o = (tid >> 3) & 1, p = tid & 7;
            const float* hr = s->xh1 + m * P1 + HD + p * 16;
            const float* wr = s->fcw[o] + p * 16;
            float a = 0.0f;
            #pragma unroll
            for (int k = 0; k < 16; k++) a = fmaf(hr[k], wr[k], a);
            a += __shfl_down_sync(0xffffffffu, a, 4, 8);
            a += __shfl_down_sync(0xffffffffu, a, 2, 8);
            a += __shfl_down_sync(0xffffffffu, a, 1, 8);
            if (p == 0) {
                a += s->fcb[o];
                out[(size_t)(bm + m) * (TDEC * NOUT) + t * NOUT + o] = a;
                s->xdec[m][o] = a;
            }
        }
        __syncthreads();   // xdec ready for next step
    }
}

extern "C" void kernel_launch(void* const* d_in, const int* in_sizes, int n_in,
                              void* d_out, int out_size)
{
    (void)in_sizes; (void)n_in; (void)out_size;
    const float* inseq = (const float*)d_in[0];
    const float* eWih0 = (const float*)d_in[1];
    const float* eWhh0 = (const float*)d_in[2];
    const float* ebih0 = (const float*)d_in[3];
    const float* ebhh0 = (const float*)d_in[4];
    const float* eWih1 = (const float*)d_in[5];
    const float* eWhh1 = (const float*)d_in[6];
    const float* ebih1 = (const float*)d_in[7];
    const float* ebhh1 = (const float*)d_in[8];
    const float* dWih0 = (const float*)d_in[9];
    const float* dWhh0 = (const float*)d_in[10];
    const float* dbih0 = (const float*)d_in[11];
    const float* dbhh0 = (const float*)d_in[12];
    const float* dWih1 = (const float*)d_in[13];
    const float* dWhh1 = (const float*)d_in[14];
    const float* dbih1 = (const float*)d_in[15];
    const float* dbhh1 = (const float*)d_in[16];
    const float* fcW   = (const float*)d_in[17];
    const float* fcb   = (const float*)d_in[18];
    float* out = (float*)d_out;

    cudaFuncSetAttribute(trajectory_lstm_kernel,
                         cudaFuncAttributeMaxDynamicSharedMemorySize,
                         (int)sizeof(Smem));

    trajectory_lstm_kernel<<<BSZ / MB, NTHREADS, sizeof(Smem)>>>(
        inseq,
        eWih0, eWhh0, ebih0, ebhh0,
        eWih1, eWhh1, ebih1, ebhh1,
        dWih0, dWhh0, dbih0, dbhh0,
        dWih1, dWhh1, dbih1, dbhh1,
        fcW, fcb, out);
}

// round 10
// speedup vs baseline: 2.1541x; 2.1541x over previous
#include <cuda_runtime.h>
#include <cuda_bf16.h>
#include <cstdint>

#define TIN  20
#define TDEC 45
#define TTOT 65
#define NTH  512
#define ROWS 64

// prepped bf16 weights: [mat]{eL0@0, dL0@131072, eL1@262144, dL1@524288}
// within mat: pass(4) x term(2:hi,lo) x n(128, gate-interleaved col) x k(K)
__device__ __align__(256) __nv_bfloat16 g_wbuf[786432];

// smem byte offsets
#define OFF_A1H 0          // 64 x 256 bf16 (hi), XOR-swizzled 16B units
#define OFF_A1L 32768
#define OFF_SH  65536      // 64 x 128 bf16 staging (hi)
#define OFF_SL  81920
#define OFF_WB  98304      // 2 x 16384 W chunk double buffer
#define OFF_XIN 131072     // 64 x 40 f32 encoder inputs
#define OFF_BIAS 141312    // 4 x 512 f32 gate-interleaved (be0,be1,bd0,bd1)
#define OFF_WX  149504     // 4 x 512 f32 (wie0,wie1,wid0,wid1)
#define OFF_FCW 157696     // 256 f32
#define OFF_FCB 158720     // 2 f32
#define OFF_XD  158728     // 64 x 2 f32
#define SMEM_TOTAL 159744

__device__ __forceinline__ uint32_t smem_u32(const void* p) {
    uint32_t a;
    asm("{ .reg .u64 t; cvta.to.shared.u64 t, %1; cvt.u32.u64 %0, t; }" : "=r"(a) : "l"(p));
    return a;
}
__device__ __forceinline__ void ldsm4(uint32_t* r, uint32_t a) {
    asm volatile("ldmatrix.sync.aligned.m8n8.x4.shared.b16 {%0,%1,%2,%3}, [%4];"
                 : "=r"(r[0]), "=r"(r[1]), "=r"(r[2]), "=r"(r[3]) : "r"(a));
}
__device__ __forceinline__ void ldsm2(uint32_t& b0, uint32_t& b1, uint32_t a) {
    asm volatile("ldmatrix.sync.aligned.m8n8.x2.shared.b16 {%0,%1}, [%2];"
                 : "=r"(b0), "=r"(b1) : "r"(a));
}
__device__ __forceinline__ void mma16816(float* d, const uint32_t* a, uint32_t b0, uint32_t b1) {
    asm volatile("mma.sync.aligned.m16n8k16.row.col.f32.bf16.bf16.f32 "
                 "{%0,%1,%2,%3}, {%4,%5,%6,%7}, {%8,%9}, {%0,%1,%2,%3};"
                 : "+f"(d[0]), "+f"(d[1]), "+f"(d[2]), "+f"(d[3])
                 : "r"(a[0]), "r"(a[1]), "r"(a[2]), "r"(a[3]), "r"(b0), "r"(b1));
}
__device__ __forceinline__ void cpasync16(uint32_t dst, const void* src) {
    asm volatile("cp.async.cg.shared.global [%0], [%1], 16;" :: "r"(dst), "l"(src));
}
__device__ __forceinline__ float sigf(float x)   { return __fdividef(1.0f, 1.0f + __expf(-x)); }
__device__ __forceinline__ float tanhf_(float x) { return 2.0f * __fdividef(1.0f, 1.0f + __expf(-2.0f * x)) - 1.0f; }

// ---------------- prep: fp32 weights -> gate-interleaved bf16 hi/lo ----------------
__global__ __launch_bounds__(256)
void prep_weights(const float* __restrict__ eWhh0, const float* __restrict__ dWhh0,
                  const float* __restrict__ eWih1, const float* __restrict__ eWhh1,
                  const float* __restrict__ dWih1, const float* __restrict__ dWhh1)
{
    int e = blockIdx.x * 256 + threadIdx.x;
    if (e >= 786432) return;
    int mat, base, K;
    if      (e < 131072) { mat = 0; base = 0;      K = 128; }
    else if (e < 262144) { mat = 1; base = 131072; K = 128; }
    else if (e < 524288) { mat = 2; base = 262144; K = 256; }
    else                 { mat = 3; base = 524288; K = 256; }
    int loc = e - base;
    int pb = 2 * K * 128;
    int pass = loc / pb, l2 = loc % pb;
    int term = l2 / (K * 128), l3 = l2 % (K * 128);
    int n = l3 / K, k = l3 % K;
    int col = pass * 128 + n;
    int orig = (col & 3) * 128 + (col >> 2);    // gate g*128 + j

    float wv;
    if      (mat == 0) wv = eWhh0[orig * 128 + k];
    else if (mat == 1) wv = dWhh0[orig * 128 + k];
    else {
        const float* Wi = (mat == 2) ? eWih1 : dWih1;
        const float* Wh = (mat == 2) ? eWhh1 : dWhh1;
        wv = (k < 128) ? Wi[orig * 128 + k] : Wh[orig * 128 + (k - 128)];
    }
    __nv_bfloat16 hi = __float2bfloat16(wv);
    g_wbuf[e] = term ? __float2bfloat16(wv - __bfloat162float(hi)) : hi;
}

// ---------------- one layer GEMM + LSTM epilogue ----------------
template <int K>
__device__ __forceinline__ void gemm_layer(
    char* sm, uint32_t sA, const __nv_bfloat16* __restrict__ wsrc,
    const float* __restrict__ bias, const float* __restrict__ wx0,
    const float* __restrict__ wx1, bool use_x,
    float xa0, float xa1, float xb0, float xb1,
    float* cst, int tid, int lane, int wn, int m0)
{
    constexpr int KC = K / 64;       // hi chunks per pass
    constexpr int NC = 2 * KC;
    const int l8 = lane & 7;
    const int bhalf = (lane >> 3) & 1;
    const int khalf = (lane >> 4) & 1;
    const int rA = m0 + (lane & 15);
    const uint32_t arowH = sA + OFF_A1H + rA * 512;
    const uint32_t arowL = sA + OFF_A1L + rA * 512;
    __nv_bfloat16* Sh = (__nv_bfloat16*)(sm + OFF_SH);
    __nv_bfloat16* Sl = (__nv_bfloat16*)(sm + OFF_SL);

    #pragma unroll
    for (int p = 0; p < 4; p++) {
        const __nv_bfloat16* wp = wsrc + p * (2 * K * 128);
        auto issue = [&](int c) {
            const int term = (c >= KC), ck = term ? c - KC : c;
            const __nv_bfloat16* sb = wp + term * (K * 128) + ck * 64;
            const uint32_t dbase = sA + OFF_WB + (c & 1) * 16384;
            #pragma unroll
            for (int i = 0; i < 2; i++) {
                const int u = tid + i * NTH;        // 0..1023
                const int n = u >> 3, cs = u & 7;
                cpasync16(dbase + n * 128 + ((uint32_t)(cs ^ (n & 7)) << 4),
                          sb + n * K + cs * 8);
            }
            asm volatile("cp.async.commit_group;" ::: "memory");
        };

        // accumulator init: bias (+ x-term for layer 0)
        float acc[4][4];
        #pragma unroll
        for (int nt = 0; nt < 4; nt++) {
            const int col0 = 128 * p + 32 * wn + 8 * nt + 2 * (lane & 3);
            const float b0 = bias[col0], b1 = bias[col0 + 1];
            if (use_x) {
                const float w00 = wx0[col0], w01 = wx0[col0 + 1];
                const float w10 = wx1[col0], w11 = wx1[col0 + 1];
                acc[nt][0] = fmaf(w10, xa1, fmaf(w00, xa0, b0));
                acc[nt][1] = fmaf(w11, xa1, fmaf(w01, xa0, b1));
                acc[nt][2] = fmaf(w10, xb1, fmaf(w00, xb0, b0));
                acc[nt][3] = fmaf(w11, xb1, fmaf(w01, xb0, b1));
            } else {
                acc[nt][0] = b0; acc[nt][1] = b1;
                acc[nt][2] = b0; acc[nt][3] = b1;
            }
        }

        issue(0);
        #pragma unroll 1
        for (int c = 0; c < NC; c++) {
            if (c + 1 < NC) {
                issue(c + 1);
                asm volatile("cp.async.wait_group 1;" ::: "memory");
            } else {
                asm volatile("cp.async.wait_group 0;" ::: "memory");
            }
            __syncthreads();
            const int term = (c >= KC);
            const int ck = term ? c - KC : c;
            const uint32_t wb = sA + OFF_WB + (c & 1) * 16384;
            #pragma unroll
            for (int ks = 0; ks < 4; ks++) {
                const uint32_t cA = (uint32_t)((8 * ck + 2 * ks + khalf) ^ l8);
                uint32_t ah[4], al[4];
                ldsm4(ah, arowH + (cA << 4));
                if (!term) ldsm4(al, arowL + (cA << 4));
                const uint32_t cB = (uint32_t)((2 * ks + bhalf) ^ l8);
                #pragma unroll
                for (int nt = 0; nt < 4; nt++) {
                    uint32_t b0, b1;
                    ldsm2(b0, b1, wb + (32 * wn + 8 * nt + l8) * 128 + (cB << 4));
                    mma16816(acc[nt], ah, b0, b1);
                    if (!term) mma16816(acc[nt], al, b0, b1);
                }
            }
            __syncthreads();
        }

        // epilogue: pair-exchange gates, LSTM cell, stage h (bf16 hi/lo) into S
        const int odd = lane & 1;
        const int rowE = m0 + (lane >> 2) + (odd ? 8 : 0);
        #pragma unroll
        for (int nt = 0; nt < 4; nt++) {
            const float e0 = __shfl_xor_sync(0xffffffffu, acc[nt][0], 1);
            const float e1 = __shfl_xor_sync(0xffffffffu, acc[nt][1], 1);
            const float e2 = __shfl_xor_sync(0xffffffffu, acc[nt][2], 1);
            const float e3 = __shfl_xor_sync(0xffffffffu, acc[nt][3], 1);
            float xi, xf, xg, xo;
            if (!odd) { xi = acc[nt][0]; xf = acc[nt][1]; xg = e0; xo = e1; }
            else      { xi = e2; xf = e3; xg = acc[nt][2]; xo = acc[nt][3]; }
            const int j = 32 * p + 8 * wn + 2 * nt + ((lane & 2) >> 1);
            const float cn = fmaf(sigf(xf), cst[p * 4 + nt], sigf(xi) * tanhf_(xg));
            cst[p * 4 + nt] = cn;
            const float h = sigf(xo) * tanhf_(cn);
            const __nv_bfloat16 hh = __float2bfloat16(h);
            const __nv_bfloat16 hl = __float2bfloat16(h - __bfloat162float(hh));
            Sh[rowE * 128 + j] = hh;
            Sl[rowE * 128 + j] = hl;
        }
    }
}

// ---------------- main kernel ----------------
__global__ void __launch_bounds__(NTH, 1)
lstm_mma_kernel(const float* __restrict__ inseq,
                const float* __restrict__ ebih0, const float* __restrict__ ebhh0,
                const float* __restrict__ ebih1, const float* __restrict__ ebhh1,
                const float* __restrict__ dbih0, const float* __restrict__ dbhh0,
                const float* __restrict__ dbih1, const float* __restrict__ dbhh1,
                const float* __restrict__ eWih0, const float* __restrict__ dWih0,
                const float* __restrict__ fcW,   const float* __restrict__ fcbp,
                float* __restrict__ out)
{
    extern __shared__ char sm[];
    const uint32_t sA = smem_u32(sm);
    float* xin    = (float*)(sm + OFF_XIN);
    float* biasgi = (float*)(sm + OFF_BIAS);
    float* wxgi   = (float*)(sm + OFF_WX);
    float* fcw    = (float*)(sm + OFF_FCW);
    float* fcb    = (float*)(sm + OFF_FCB);
    float* xdec   = (float*)(sm + OFF_XD);
    __nv_bfloat16* Sh = (__nv_bfloat16*)(sm + OFF_SH);
    __nv_bfloat16* Sl = (__nv_bfloat16*)(sm + OFF_SL);

    const int tid = threadIdx.x;
    const int lane = tid & 31, w = tid >> 5;
    const int wm = w >> 2, wn = w & 3;
    const int m0 = 16 * wm;
    const int bm = blockIdx.x * ROWS;

    // ---- one-time init ----
    for (int i = tid; i < ROWS * 40; i += NTH) {
        const int r = i / 40, q = i % 40;
        xin[i] = inseq[(size_t)(bm + r) * 40 + q];
    }
    {
        const int col = tid;                      // NTH == 512
        const int orig = (col & 3) * 128 + (col >> 2);
        biasgi[col]        = ebih0[orig] + ebhh0[orig];
        biasgi[512 + col]  = ebih1[orig] + ebhh1[orig];
        biasgi[1024 + col] = dbih0[orig] + dbhh0[orig];
        biasgi[1536 + col] = dbih1[orig] + dbhh1[orig];
        wxgi[col]        = eWih0[2 * orig];
        wxgi[512 + col]  = eWih0[2 * orig + 1];
        wxgi[1024 + col] = dWih0[2 * orig];
        wxgi[1536 + col] = dWih0[2 * orig + 1];
    }
    if (tid < 256) fcw[tid] = fcW[tid];
    if (tid < 2)   fcb[tid] = fcbp[tid];
    if (tid < 2 * ROWS)
        xdec[tid] = inseq[(size_t)(bm + (tid >> 1)) * 40 + 38 + (tid & 1)];
    for (int i = tid; i < 16384; i += NTH)        // zero A1 hi+lo (64KB)
        ((uint32_t*)(sm + OFF_A1H))[i] = 0u;
    __syncthreads();

    float c0[16], c1[16];
    #pragma unroll
    for (int i = 0; i < 16; i++) { c0[i] = 0.0f; c1[i] = 0.0f; }

    // S -> A1 copy with swizzle; koff = 0 (layer0 cols) or 16 (layer1 cols)
    auto copyS = [&](int koff) {
        #pragma unroll
        for (int i = 0; i < 2; i++) {
            const int u = tid + i * NTH;          // 0..1023
            const int r = u >> 4, cs = u & 15;
            const uint4 vh = ((const uint4*)(sm + OFF_SH))[u];
            const uint4 vl = ((const uint4*)(sm + OFF_SL))[u];
            const int dc = (koff + cs) ^ (r & 7);
            ((uint4*)(sm + OFF_A1H))[r * 32 + dc] = vh;
            ((uint4*)(sm + OFF_A1L))[r * 32 + dc] = vl;
        }
    };

    const int ra = m0 + (lane >> 2), rb = ra + 8;

    for (int t = 0; t < TTOT; t++) {
        const bool enc = t < TIN;
        float xa0, xa1, xb0, xb1;
        if (enc) {
            xa0 = xin[ra * 40 + 2 * t]; xa1 = xin[ra * 40 + 2 * t + 1];
            xb0 = xin[rb * 40 + 2 * t]; xb1 = xin[rb * 40 + 2 * t + 1];
        } else {
            xa0 = xdec[ra * 2]; xa1 = xdec[ra * 2 + 1];
            xb0 = xdec[rb * 2]; xb1 = xdec[rb * 2 + 1];
        }
        // ---- layer 0 (K=128, reads A1 cols 0:128 = h0 old) ----
        gemm_layer<128>(sm, sA, g_wbuf + (enc ? 0 : 131072),
                        biasgi + (enc ? 0 : 1024),
                        wxgi + (enc ? 0 : 1024), wxgi + (enc ? 512 : 1536), true,
                        xa0, xa1, xb0, xb1, c0, tid, lane, wn, m0);
        __syncthreads();
        copyS(0);                 // h0 new -> A1 cols 0:128
        __syncthreads();
        // ---- layer 1 (K=256, reads [h0 new | h1 old]) ----
        gemm_layer<256>(sm, sA, g_wbuf + (enc ? 262144 : 524288),
                        biasgi + (enc ? 512 : 1536),
                        nullptr, nullptr, false,
                        0.0f, 0.0f, 0.0f, 0.0f, c1, tid, lane, wn, m0);
        __syncthreads();
        copyS(16);                // h1 new -> A1 cols 128:256
        // ---- fc head (decoder steps): exact hi+lo reconstruction ----
        if (!enc && tid < 2 * ROWS) {
            const int r = tid >> 1, o = tid & 1;
            float a = fcb[o];
            const __nv_bfloat16* sh = Sh + r * 128;
            const __nv_bfloat16* sl = Sl + r * 128;
            #pragma unroll 8
            for (int j = 0; j < 128; j++)
                a = fmaf(__bfloat162float(sh[j]) + __bfloat162float(sl[j]),
                         fcw[o * 128 + j], a);
            out[(size_t)(bm + r) * (TDEC * 2) + (t - TIN) * 2 + o] = a;
            xdec[tid] = a;
        }
        __syncthreads();
    }
}

extern "C" void kernel_launch(void* const* d_in, const int* in_sizes, int n_in,
                              void* d_out, int out_size)
{
    (void)in_sizes; (void)n_in; (void)out_size;
    const float* inseq = (const float*)d_in[0];
    const float* eWih0 = (const float*)d_in[1];
    const float* eWhh0 = (const float*)d_in[2];
    const float* ebih0 = (const float*)d_in[3];
    const float* ebhh0 = (const float*)d_in[4];
    const float* eWih1 = (const float*)d_in[5];
    const float* eWhh1 = (const float*)d_in[6];
    const float* ebih1 = (const float*)d_in[7];
    const float* ebhh1 = (const float*)d_in[8];
    const float* dWih0 = (const float*)d_in[9];
    const float* dWhh0 = (const float*)d_in[10];
    const float* dbih0 = (const float*)d_in[11];
    const float* dbhh0 = (const float*)d_in[12];
    const float* dWih1 = (const float*)d_in[13];
    const float* dWhh1 = (const float*)d_in[14];
    const float* dbih1 = (const float*)d_in[15];
    const float* dbhh1 = (const float*)d_in[16];
    const float* fcW   = (const float*)d_in[17];
    const float* fcb   = (const float*)d_in[18];
    float* out = (float*)d_out;

    prep_weights<<<3072, 256>>>(eWhh0, dWhh0, eWih1, eWhh1, dWih1, dWhh1);

    cudaFuncSetAttribute(lstm_mma_kernel,
                         cudaFuncAttributeMaxDynamicSharedMemorySize, SMEM_TOTAL);
    lstm_mma_kernel<<<32768 / ROWS, NTH, SMEM_TOTAL>>>(
        inseq,
        ebih0, ebhh0, ebih1, ebhh1,
        dbih0, dbhh0, dbih1, dbhh1,
        eWih0, dWih0, fcW, fcb, out);
}

// round 11
// speedup vs baseline: 2.6215x; 1.2170x over previous
#include <cuda_runtime.h>
#include <cuda_bf16.h>
#include <cstdint>

#define TIN  20
#define TDEC 45
#define TTOT 65
#define NTH  256
#define ROWS 32

// prepped bf16 weights: [mat]{eL0@0, dL0@131072, eL1@262144, dL1@524288}
// within mat: pass(4) x term(2:hi,lo) x n(128, gate-interleaved col) x k(K)
__device__ __align__(256) __nv_bfloat16 g_wbuf[786432];

// smem byte offsets (per-CTA total ~104.9KB -> 2 CTAs/SM)
#define OFF_A1H 0          // 32 x 256 bf16 (hi), XOR-swizzled 16B units
#define OFF_A1L 16384
#define OFF_SH  32768      // 32 x 128 bf16 staging (hi)
#define OFF_SL  40960
#define OFF_WB  49152      // 2 x 16384 W chunk double buffer
#define OFF_XIN 81920      // 32 x 40 f32 encoder inputs
#define OFF_BIAS 87040     // 4 x 512 f32 gate-interleaved
#define OFF_WX  95232      // 4 x 512 f32
#define OFF_FCW 103424     // 256 f32
#define OFF_FCB 104448     // 2 f32
#define OFF_XD  104456     // 32 x 2 f32
#define SMEM_TOTAL 104960

__device__ __forceinline__ uint32_t smem_u32(const void* p) {
    uint32_t a;
    asm("{ .reg .u64 t; cvta.to.shared.u64 t, %1; cvt.u32.u64 %0, t; }" : "=r"(a) : "l"(p));
    return a;
}
__device__ __forceinline__ void ldsm4(uint32_t* r, uint32_t a) {
    asm volatile("ldmatrix.sync.aligned.m8n8.x4.shared.b16 {%0,%1,%2,%3}, [%4];"
                 : "=r"(r[0]), "=r"(r[1]), "=r"(r[2]), "=r"(r[3]) : "r"(a));
}
__device__ __forceinline__ void ldsm2(uint32_t& b0, uint32_t& b1, uint32_t a) {
    asm volatile("ldmatrix.sync.aligned.m8n8.x2.shared.b16 {%0,%1}, [%2];"
                 : "=r"(b0), "=r"(b1) : "r"(a));
}
__device__ __forceinline__ void mma16816(float* d, const uint32_t* a, uint32_t b0, uint32_t b1) {
    asm volatile("mma.sync.aligned.m16n8k16.row.col.f32.bf16.bf16.f32 "
                 "{%0,%1,%2,%3}, {%4,%5,%6,%7}, {%8,%9}, {%0,%1,%2,%3};"
                 : "+f"(d[0]), "+f"(d[1]), "+f"(d[2]), "+f"(d[3])
                 : "r"(a[0]), "r"(a[1]), "r"(a[2]), "r"(a[3]), "r"(b0), "r"(b1));
}
__device__ __forceinline__ void cpasync16(uint32_t dst, const void* src) {
    asm volatile("cp.async.cg.shared.global [%0], [%1], 16;" :: "r"(dst), "l"(src));
}
__device__ __forceinline__ float sigf(float x)   { return __fdividef(1.0f, 1.0f + __expf(-x)); }
__device__ __forceinline__ float tanhf_(float x) { return 2.0f * __fdividef(1.0f, 1.0f + __expf(-2.0f * x)) - 1.0f; }

// ---------------- prep: fp32 weights -> gate-interleaved bf16 hi/lo ----------------
__global__ __launch_bounds__(256)
void prep_weights(const float* __restrict__ eWhh0, const float* __restrict__ dWhh0,
                  const float* __restrict__ eWih1, const float* __restrict__ eWhh1,
                  const float* __restrict__ dWih1, const float* __restrict__ dWhh1)
{
    int e = blockIdx.x * 256 + threadIdx.x;
    if (e >= 786432) return;
    int mat, base, K;
    if      (e < 131072) { mat = 0; base = 0;      K = 128; }
    else if (e < 262144) { mat = 1; base = 131072; K = 128; }
    else if (e < 524288) { mat = 2; base = 262144; K = 256; }
    else                 { mat = 3; base = 524288; K = 256; }
    int loc = e - base;
    int pb = 2 * K * 128;
    int pass = loc / pb, l2 = loc % pb;
    int term = l2 / (K * 128), l3 = l2 % (K * 128);
    int n = l3 / K, k = l3 % K;
    int col = pass * 128 + n;
    int orig = (col & 3) * 128 + (col >> 2);    // gate g*128 + j

    float wv;
    if      (mat == 0) wv = eWhh0[orig * 128 + k];
    else if (mat == 1) wv = dWhh0[orig * 128 + k];
    else {
        const float* Wi = (mat == 2) ? eWih1 : dWih1;
        const float* Wh = (mat == 2) ? eWhh1 : dWhh1;
        wv = (k < 128) ? Wi[orig * 128 + k] : Wh[orig * 128 + (k - 128)];
    }
    __nv_bfloat16 hi = __float2bfloat16(wv);
    g_wbuf[e] = term ? __float2bfloat16(wv - __bfloat162float(hi)) : hi;
}

// ---------------- one layer GEMM + LSTM epilogue ----------------
template <int K>
__device__ __forceinline__ void gemm_layer(
    char* sm, uint32_t sA, const __nv_bfloat16* __restrict__ wsrc,
    const float* __restrict__ bias, const float* __restrict__ wx0,
    const float* __restrict__ wx1, bool use_x,
    float xa0, float xa1, float xb0, float xb1,
    float* cst, int tid, int lane, int wn, int m0)
{
    constexpr int KC = K / 64;       // hi chunks per pass
    constexpr int NC = 2 * KC;
    const int l8 = lane & 7;
    const int bhalf = (lane >> 3) & 1;
    const int khalf = (lane >> 4) & 1;
    const int rA = m0 + (lane & 15);
    const uint32_t arowH = sA + OFF_A1H + rA * 512;
    const uint32_t arowL = sA + OFF_A1L + rA * 512;
    __nv_bfloat16* Sh = (__nv_bfloat16*)(sm + OFF_SH);
    __nv_bfloat16* Sl = (__nv_bfloat16*)(sm + OFF_SL);

    #pragma unroll
    for (int p = 0; p < 4; p++) {
        const __nv_bfloat16* wp = wsrc + p * (2 * K * 128);
        auto issue = [&](int c) {
            const int term = (c >= KC), ck = term ? c - KC : c;
            const __nv_bfloat16* sb = wp + term * (K * 128) + ck * 64;
            const uint32_t dbase = sA + OFF_WB + (c & 1) * 16384;
            #pragma unroll
            for (int i = 0; i < 4; i++) {
                const int u = tid + i * NTH;        // 0..1023
                const int n = u >> 3, cs = u & 7;
                cpasync16(dbase + n * 128 + ((uint32_t)(cs ^ (n & 7)) << 4),
                          sb + n * K + cs * 8);
            }
            asm volatile("cp.async.commit_group;" ::: "memory");
        };

        // accumulator init: bias (+ x-term for layer 0)
        float acc[4][4];
        #pragma unroll
        for (int nt = 0; nt < 4; nt++) {
            const int col0 = 128 * p + 32 * wn + 8 * nt + 2 * (lane & 3);
            const float b0 = bias[col0], b1 = bias[col0 + 1];
            if (use_x) {
                const float w00 = wx0[col0], w01 = wx0[col0 + 1];
                const float w10 = wx1[col0], w11 = wx1[col0 + 1];
                acc[nt][0] = fmaf(w10, xa1, fmaf(w00, xa0, b0));
                acc[nt][1] = fmaf(w11, xa1, fmaf(w01, xa0, b1));
                acc[nt][2] = fmaf(w10, xb1, fmaf(w00, xb0, b0));
                acc[nt][3] = fmaf(w11, xb1, fmaf(w01, xb0, b1));
            } else {
                acc[nt][0] = b0; acc[nt][1] = b1;
                acc[nt][2] = b0; acc[nt][3] = b1;
            }
        }

        issue(0);
        #pragma unroll 1
        for (int c = 0; c < NC; c++) {
            if (c + 1 < NC) {
                issue(c + 1);
                asm volatile("cp.async.wait_group 1;" ::: "memory");
            } else {
                asm volatile("cp.async.wait_group 0;" ::: "memory");
            }
            __syncthreads();
            const int term = (c >= KC);
            const int ck = term ? c - KC : c;
            const uint32_t wb = sA + OFF_WB + (c & 1) * 16384;
            #pragma unroll
            for (int ks = 0; ks < 4; ks++) {
                const uint32_t cA = (uint32_t)((8 * ck + 2 * ks + khalf) ^ l8);
                uint32_t ah[4], al[4];
                ldsm4(ah, arowH + (cA << 4));
                if (!term) ldsm4(al, arowL + (cA << 4));
                const uint32_t cB = (uint32_t)((2 * ks + bhalf) ^ l8);
                #pragma unroll
                for (int nt = 0; nt < 4; nt++) {
                    uint32_t b0, b1;
                    ldsm2(b0, b1, wb + (32 * wn + 8 * nt + l8) * 128 + (cB << 4));
                    mma16816(acc[nt], ah, b0, b1);
                    if (!term) mma16816(acc[nt], al, b0, b1);
                }
            }
            __syncthreads();
        }

        // epilogue: pair-exchange gates, LSTM cell, stage h (bf16 hi/lo) into S
        const int odd = lane & 1;
        const int rowE = m0 + (lane >> 2) + (odd ? 8 : 0);
        #pragma unroll
        for (int nt = 0; nt < 4; nt++) {
            const float e0 = __shfl_xor_sync(0xffffffffu, acc[nt][0], 1);
            const float e1 = __shfl_xor_sync(0xffffffffu, acc[nt][1], 1);
            const float e2 = __shfl_xor_sync(0xffffffffu, acc[nt][2], 1);
            const float e3 = __shfl_xor_sync(0xffffffffu, acc[nt][3], 1);
            float xi, xf, xg, xo;
            if (!odd) { xi = acc[nt][0]; xf = acc[nt][1]; xg = e0; xo = e1; }
            else      { xi = e2; xf = e3; xg = acc[nt][2]; xo = acc[nt][3]; }
            const int j = 32 * p + 8 * wn + 2 * nt + ((lane & 2) >> 1);
            const float cn = fmaf(sigf(xf), cst[p * 4 + nt], sigf(xi) * tanhf_(xg));
            cst[p * 4 + nt] = cn;
            const float h = sigf(xo) * tanhf_(cn);
            const __nv_bfloat16 hh = __float2bfloat16(h);
            const __nv_bfloat16 hl = __float2bfloat16(h - __bfloat162float(hh));
            Sh[rowE * 128 + j] = hh;
            Sl[rowE * 128 + j] = hl;
        }
    }
}

// ---------------- main kernel ----------------
__global__ void __launch_bounds__(NTH, 2)
lstm_mma_kernel(const float* __restrict__ inseq,
                const float* __restrict__ ebih0, const float* __restrict__ ebhh0,
                const float* __restrict__ ebih1, const float* __restrict__ ebhh1,
                const float* __restrict__ dbih0, const float* __restrict__ dbhh0,
                const float* __restrict__ dbih1, const float* __restrict__ dbhh1,
                const float* __restrict__ eWih0, const float* __restrict__ dWih0,
                const float* __restrict__ fcW,   const float* __restrict__ fcbp,
                float* __restrict__ out)
{
    extern __shared__ char sm[];
    const uint32_t sA = smem_u32(sm);
    float* xin    = (float*)(sm + OFF_XIN);
    float* biasgi = (float*)(sm + OFF_BIAS);
    float* wxgi   = (float*)(sm + OFF_WX);
    float* fcw    = (float*)(sm + OFF_FCW);
    float* fcb    = (float*)(sm + OFF_FCB);
    float* xdec   = (float*)(sm + OFF_XD);
    __nv_bfloat16* Sh = (__nv_bfloat16*)(sm + OFF_SH);
    __nv_bfloat16* Sl = (__nv_bfloat16*)(sm + OFF_SL);

    const int tid = threadIdx.x;
    const int lane = tid & 31, w = tid >> 5;
    const int wm = w >> 2, wn = w & 3;
    const int m0 = 16 * wm;
    const int bm = blockIdx.x * ROWS;

    // ---- one-time init ----
    for (int i = tid; i < ROWS * 40; i += NTH) {
        const int r = i / 40, q = i % 40;
        xin[i] = inseq[(size_t)(bm + r) * 40 + q];
    }
    for (int col = tid; col < 512; col += NTH) {
        const int orig = (col & 3) * 128 + (col >> 2);
        biasgi[col]        = ebih0[orig] + ebhh0[orig];
        biasgi[512 + col]  = ebih1[orig] + ebhh1[orig];
        biasgi[1024 + col] = dbih0[orig] + dbhh0[orig];
        biasgi[1536 + col] = dbih1[orig] + dbhh1[orig];
        wxgi[col]        = eWih0[2 * orig];
        wxgi[512 + col]  = eWih0[2 * orig + 1];
        wxgi[1024 + col] = dWih0[2 * orig];
        wxgi[1536 + col] = dWih0[2 * orig + 1];
    }
    if (tid < 256) fcw[tid] = fcW[tid];
    if (tid < 2)   fcb[tid] = fcbp[tid];
    if (tid < 2 * ROWS)
        xdec[tid] = inseq[(size_t)(bm + (tid >> 1)) * 40 + 38 + (tid & 1)];
    for (int i = tid; i < 8192; i += NTH)         // zero A1 hi+lo (32KB)
        ((uint32_t*)(sm + OFF_A1H))[i] = 0u;
    __syncthreads();

    float c0[16], c1[16];
    #pragma unroll
    for (int i = 0; i < 16; i++) { c0[i] = 0.0f; c1[i] = 0.0f; }

    // S -> A1 copy with swizzle; koff = 0 (layer0 cols) or 16 (layer1 cols)
    auto copyS = [&](int koff) {
        #pragma unroll
        for (int i = 0; i < 2; i++) {
            const int u = tid + i * NTH;          // 0..511
            const int r = u >> 4, cs = u & 15;
            const uint4 vh = ((const uint4*)(sm + OFF_SH))[u];
            const uint4 vl = ((const uint4*)(sm + OFF_SL))[u];
            const int dc = (koff + cs) ^ (r & 7);
            ((uint4*)(sm + OFF_A1H))[r * 32 + dc] = vh;
            ((uint4*)(sm + OFF_A1L))[r * 32 + dc] = vl;
        }
    };

    const int ra = m0 + (lane >> 2), rb = ra + 8;

    for (int t = 0; t < TTOT; t++) {
        const bool enc = t < TIN;
        float xa0, xa1, xb0, xb1;
        if (enc) {
            xa0 = xin[ra * 40 + 2 * t]; xa1 = xin[ra * 40 + 2 * t + 1];
            xb0 = xin[rb * 40 + 2 * t]; xb1 = xin[rb * 40 + 2 * t + 1];
        } else {
            xa0 = xdec[ra * 2]; xa1 = xdec[ra * 2 + 1];
            xb0 = xdec[rb * 2]; xb1 = xdec[rb * 2 + 1];
        }
        // ---- layer 0 (K=128, reads A1 cols 0:128 = h0 old) ----
        gemm_layer<128>(sm, sA, g_wbuf + (enc ? 0 : 131072),
                        biasgi + (enc ? 0 : 1024),
                        wxgi + (enc ? 0 : 1024), wxgi + (enc ? 512 : 1536), true,
                        xa0, xa1, xb0, xb1, c0, tid, lane, wn, m0);
        __syncthreads();
        copyS(0);                 // h0 new -> A1 cols 0:128
        __syncthreads();
        // ---- layer 1 (K=256, reads [h0 new | h1 old]) ----
        gemm_layer<256>(sm, sA, g_wbuf + (enc ? 262144 : 524288),
                        biasgi + (enc ? 512 : 1536),
                        nullptr, nullptr, false,
                        0.0f, 0.0f, 0.0f, 0.0f, c1, tid, lane, wn, m0);
        __syncthreads();
        copyS(16);                // h1 new -> A1 cols 128:256
        // ---- fc head (decoder steps): exact hi+lo reconstruction ----
        if (!enc && tid < 2 * ROWS) {
            const int r = tid >> 1, o = tid & 1;
            float a = fcb[o];
            const __nv_bfloat16* sh = Sh + r * 128;
            const __nv_bfloat16* sl = Sl + r * 128;
            #pragma unroll 8
            for (int j = 0; j < 128; j++)
                a = fmaf(__bfloat162float(sh[j]) + __bfloat162float(sl[j]),
                         fcw[o * 128 + j], a);
            out[(size_t)(bm + r) * (TDEC * 2) + (t - TIN) * 2 + o] = a;
            xdec[tid] = a;
        }
        __syncthreads();
    }
}

extern "C" void kernel_launch(void* const* d_in, const int* in_sizes, int n_in,
                              void* d_out, int out_size)
{
    (void)in_sizes; (void)n_in; (void)out_size;
    const float* inseq = (const float*)d_in[0];
    const float* eWih0 = (const float*)d_in[1];
    const float* eWhh0 = (const float*)d_in[2];
    const float* ebih0 = (const float*)d_in[3];
    const float* ebhh0 = (const float*)d_in[4];
    const float* eWih1 = (const float*)d_in[5];
    const float* eWhh1 = (const float*)d_in[6];
    const float* ebih1 = (const float*)d_in[7];
    const float* ebhh1 = (const float*)d_in[8];
    const float* dWih0 = (const float*)d_in[9];
    const float* dWhh0 = (const float*)d_in[10];
    const float* dbih0 = (const float*)d_in[11];
    const float* dbhh0 = (const float*)d_in[12];
    const float* dWih1 = (const float*)d_in[13];
    const float* dWhh1 = (const float*)d_in[14];
    const float* dbih1 = (const float*)d_in[15];
    const float* dbhh1 = (const float*)d_in[16];
    const float* fcW   = (const float*)d_in[17];
    const float* fcb   = (const float*)d_in[18];
    float* out = (float*)d_out;

    prep_weights<<<3072, 256>>>(eWhh0, dWhh0, eWih1, eWhh1, dWih1, dWhh1);

    cudaFuncSetAttribute(lstm_mma_kernel,
                         cudaFuncAttributeMaxDynamicSharedMemorySize, SMEM_TOTAL);
    lstm_mma_kernel<<<32768 / ROWS, NTH, SMEM_TOTAL>>>(
        inseq,
        ebih0, ebhh0, ebih1, ebhh1,
        dbih0, dbhh0, dbih1, dbhh1,
        eWih0, dWih0, fcW, fcb, out);
}

// round 12
// speedup vs baseline: 3.5153x; 1.3409x over previous
#include <cuda_runtime.h>
#include <cuda_bf16.h>
#include <cstdint>

#define TIN  20
#define TDEC 45
#define TTOT 65
#define NTH  256
#define ROWS 32

// prepped bf16 weights: mats {eL0@0, dL0@131072, eL1@262144, dL1@524288}
// within mat: chunk(=pass*NCK+ck, 8192 elems) : [term(2)][n(128)][k(32)]
__device__ __align__(256) __nv_bfloat16 g_wbuf[786432];
// prepped f32 tables: be0@0 be1@512 bd0@1024 bd1@1536 | wie0@2048 wie1@2560 wid0@3072 wid1@3584
__device__ __align__(256) float g_tbl[4096];

// smem byte offsets (~105.4 KB/CTA -> 2 CTAs/SM)
#define OFF_A1H 0          // 32 x 256 bf16 (hi), XOR-swizzled 16B units
#define OFF_A1L 16384
#define OFF_SP  32768      // 32 x 128 u32 packed (hh | hl<<16) staging
#define OFF_WB  49152      // 3 x 16384 W chunk triple buffer
#define OFF_TBL 98304      // staged: biasL0[512] biasL1[512] wx0[512] wx1[512]
#define OFF_FCW 106496     // 256 f32
#define OFF_FCB 107520
#define OFF_XD  107536     // 32 x 2 f32
#define SMEM_TOTAL 107904

__device__ __forceinline__ uint32_t smem_u32(const void* p) {
    uint32_t a;
    asm("{ .reg .u64 t; cvta.to.shared.u64 t, %1; cvt.u32.u64 %0, t; }" : "=r"(a) : "l"(p));
    return a;
}
__device__ __forceinline__ void ldsm4(uint32_t* r, uint32_t a) {
    asm volatile("ldmatrix.sync.aligned.m8n8.x4.shared.b16 {%0,%1,%2,%3}, [%4];"
                 : "=r"(r[0]), "=r"(r[1]), "=r"(r[2]), "=r"(r[3]) : "r"(a));
}
__device__ __forceinline__ void mma16816(float* d, const uint32_t* a, uint32_t b0, uint32_t b1) {
    asm volatile("mma.sync.aligned.m16n8k16.row.col.f32.bf16.bf16.f32 "
                 "{%0,%1,%2,%3}, {%4,%5,%6,%7}, {%8,%9}, {%0,%1,%2,%3};"
                 : "+f"(d[0]), "+f"(d[1]), "+f"(d[2]), "+f"(d[3])
                 : "r"(a[0]), "r"(a[1]), "r"(a[2]), "r"(a[3]), "r"(b0), "r"(b1));
}
__device__ __forceinline__ void cpasync16(uint32_t dst, const void* src) {
    asm volatile("cp.async.cg.shared.global [%0], [%1], 16;" :: "r"(dst), "l"(src));
}
__device__ __forceinline__ float sigf(float x)   { return __fdividef(1.0f, 1.0f + __expf(-x)); }
__device__ __forceinline__ float tanhf_(float x) { return 2.0f * __fdividef(1.0f, 1.0f + __expf(-2.0f * x)) - 1.0f; }

// ---------------- prep kernels ----------------
__global__ __launch_bounds__(256)
void prep_weights(const float* __restrict__ eWhh0, const float* __restrict__ dWhh0,
                  const float* __restrict__ eWih1, const float* __restrict__ eWhh1,
                  const float* __restrict__ dWih1, const float* __restrict__ dWhh1)
{
    int e = blockIdx.x * 256 + threadIdx.x;
    if (e >= 786432) return;
    int mat, base, K;
    if      (e < 131072) { mat = 0; base = 0;      K = 128; }
    else if (e < 262144) { mat = 1; base = 131072; K = 128; }
    else if (e < 524288) { mat = 2; base = 262144; K = 256; }
    else                 { mat = 3; base = 524288; K = 256; }
    int loc = e - base;
    int chunk = loc >> 13, rem = loc & 8191;
    int tt = rem >> 12;
    int n = (rem >> 5) & 127;
    int k = rem & 31;
    int nck = K / 32;
    int p = chunk / nck, ck = chunk % nck;
    int col = p * 128 + n;
    int orig = (col & 3) * 128 + (col >> 2);    // gate g*128 + j
    int kg = ck * 32 + k;

    float wv;
    if      (mat == 0) wv = eWhh0[orig * 128 + kg];
    else if (mat == 1) wv = dWhh0[orig * 128 + kg];
    else {
        const float* Wi = (mat == 2) ? eWih1 : dWih1;
        const float* Wh = (mat == 2) ? eWhh1 : dWhh1;
        wv = (kg < 128) ? Wi[orig * 128 + kg] : Wh[orig * 128 + (kg - 128)];
    }
    __nv_bfloat16 hi = __float2bfloat16(wv);
    g_wbuf[e] = tt ? __float2bfloat16(wv - __bfloat162float(hi)) : hi;
}

__global__ __launch_bounds__(256)
void prep_tables(const float* __restrict__ ebih0, const float* __restrict__ ebhh0,
                 const float* __restrict__ ebih1, const float* __restrict__ ebhh1,
                 const float* __restrict__ dbih0, const float* __restrict__ dbhh0,
                 const float* __restrict__ dbih1, const float* __restrict__ dbhh1,
                 const float* __restrict__ eWih0, const float* __restrict__ dWih0)
{
    int i = blockIdx.x * 256 + threadIdx.x;
    if (i >= 4096) return;
    int col = i & 511;
    int orig = (col & 3) * 128 + (col >> 2);
    int seg = i >> 9;
    float v;
    switch (seg) {
        case 0: v = ebih0[orig] + ebhh0[orig]; break;
        case 1: v = ebih1[orig] + ebhh1[orig]; break;
        case 2: v = dbih0[orig] + dbhh0[orig]; break;
        case 3: v = dbih1[orig] + dbhh1[orig]; break;
        case 4: v = eWih0[2 * orig];     break;
        case 5: v = eWih0[2 * orig + 1]; break;
        case 6: v = dWih0[2 * orig];     break;
        default: v = dWih0[2 * orig + 1]; break;
    }
    g_tbl[i] = v;
}

// ---------------- one layer: GEMM (merged terms) + per-pass LSTM epilogue ----------------
template <int K>
__device__ __forceinline__ void gemm_layer(
    char* sm, uint32_t sA, const __nv_bfloat16* __restrict__ wsrc,
    const float* __restrict__ bias, const float* __restrict__ wx0,
    const float* __restrict__ wx1, bool use_x,
    float xa0, float xa1, float xb0, float xb1,
    float* cst, int tid, int lane, int wn, int m0)
{
    constexpr int NCK = K / 32;          // chunks per pass
    constexpr int NCT = 4 * NCK;         // total chunks in layer
    const int l8 = lane & 7;
    const int g2 = lane >> 3;
    const int khalf = (lane >> 4) & 1;
    const int rA = m0 + (lane & 15);
    const uint32_t arowH = sA + OFF_A1H + rA * 512;
    const uint32_t arowL = sA + OFF_A1L + rA * 512;

    auto issue = [&](int ci) {
        const __nv_bfloat16* src = wsrc + (size_t)ci * 8192;
        const uint32_t dbase = sA + OFF_WB + (uint32_t)(ci % 3) * 16384u;
        #pragma unroll
        for (int i = 0; i < 4; i++) {
            const int u = tid + i * NTH;          // 0..1023 16B units
            const int n = (u >> 2) & 127, kc8 = u & 3, tt = u >> 9;
            cpasync16(dbase + tt * 8192 + n * 64 +
                          ((uint32_t)(kc8 ^ ((n >> 1) & 3)) << 4),
                      src + (size_t)u * 8);
        }
        asm volatile("cp.async.commit_group;" ::: "memory");
    };

    issue(0);
    issue(1);

    #pragma unroll 1
    for (int p = 0; p < 4; p++) {
        // accumulator init: bias (+ x-term for layer 0)
        float acc[4][4];
        #pragma unroll
        for (int nt = 0; nt < 4; nt++) {
            const int col0 = 128 * p + 32 * wn + 8 * nt + 2 * (lane & 3);
            const float b0 = bias[col0], b1 = bias[col0 + 1];
            if (use_x) {
                const float w00 = wx0[col0], w01 = wx0[col0 + 1];
                const float w10 = wx1[col0], w11 = wx1[col0 + 1];
                acc[nt][0] = fmaf(w10, xa1, fmaf(w00, xa0, b0));
                acc[nt][1] = fmaf(w11, xa1, fmaf(w01, xa0, b1));
                acc[nt][2] = fmaf(w10, xb1, fmaf(w00, xb0, b0));
                acc[nt][3] = fmaf(w11, xb1, fmaf(w01, xb0, b1));
            } else {
                acc[nt][0] = b0; acc[nt][1] = b1;
                acc[nt][2] = b0; acc[nt][3] = b1;
            }
        }

        #pragma unroll 1
        for (int ck = 0; ck < NCK; ck++) {
            const int ci = p * NCK + ck;
            if (ci == NCT - 1) asm volatile("cp.async.wait_group 0;" ::: "memory");
            else               asm volatile("cp.async.wait_group 1;" ::: "memory");
            __syncthreads();
            if (ci + 2 < NCT) issue(ci + 2);
            const uint32_t wb = sA + OFF_WB + (uint32_t)(ci % 3) * 16384u;
            #pragma unroll
            for (int ks = 0; ks < 2; ks++) {
                const uint32_t cA = (uint32_t)((4 * ck + 2 * ks + khalf) ^ l8);
                uint32_t ah[4], al[4];
                ldsm4(ah, arowH + (cA << 4));
                ldsm4(al, arowL + (cA << 4));
                #pragma unroll
                for (int q = 0; q < 2; q++) {
                    const int n_row = 32 * wn + 16 * q + 8 * (g2 >> 1) + l8;
                    const int kc8v = 2 * ks + (g2 & 1);
                    const uint32_t off = (uint32_t)(n_row * 64) +
                        ((uint32_t)(kc8v ^ ((n_row >> 1) & 3)) << 4);
                    uint32_t bh[4], bl[4];
                    ldsm4(bh, wb + off);
                    ldsm4(bl, wb + 8192 + off);
                    mma16816(acc[2 * q],     ah, bh[0], bh[1]);
                    mma16816(acc[2 * q],     al, bh[0], bh[1]);
                    mma16816(acc[2 * q],     ah, bl[0], bl[1]);
                    mma16816(acc[2 * q + 1], ah, bh[2], bh[3]);
                    mma16816(acc[2 * q + 1], al, bh[2], bh[3]);
                    mma16816(acc[2 * q + 1], ah, bl[2], bl[3]);
                }
            }
        }

        // epilogue pass p: gates -> (c,h); pack h as bf16 hi/lo into staging
        const int odd = lane & 1;
        const int rowE = m0 + (lane >> 2) + (odd ? 8 : 0);
        uint32_t myv[4], pva[4];
        #pragma unroll
        for (int nt = 0; nt < 4; nt++) {
            const float e0 = __shfl_xor_sync(0xffffffffu, acc[nt][0], 1);
            const float e1 = __shfl_xor_sync(0xffffffffu, acc[nt][1], 1);
            const float e2 = __shfl_xor_sync(0xffffffffu, acc[nt][2], 1);
            const float e3 = __shfl_xor_sync(0xffffffffu, acc[nt][3], 1);
            float xi, xf, xg, xo;
            if (!odd) { xi = acc[nt][0]; xf = acc[nt][1]; xg = e0; xo = e1; }
            else      { xi = e2; xf = e3; xg = acc[nt][2]; xo = acc[nt][3]; }
            const float cn = fmaf(sigf(xf), cst[p * 4 + nt], sigf(xi) * tanhf_(xg));
            cst[p * 4 + nt] = cn;
            const float h = sigf(xo) * tanhf_(cn);
            const uint32_t hh = (uint32_t)__bfloat16_as_ushort(__float2bfloat16(h));
            const float hb = __uint_as_float(hh << 16);
            const uint32_t hl = (uint32_t)__bfloat16_as_ushort(__float2bfloat16(h - hb));
            const uint32_t v = hh | (hl << 16);
            myv[nt] = v;
            pva[nt] = __shfl_xor_sync(0xffffffffu, v, 2);
        }
        if ((lane & 2) == 0) {
            uint32_t* Sp = (uint32_t*)(sm + OFF_SP) + rowE * 128 + 32 * p + 8 * wn;
            ((uint4*)Sp)[0] = make_uint4(myv[0], pva[0], myv[1], pva[1]);
            ((uint4*)Sp)[1] = make_uint4(myv[2], pva[2], myv[3], pva[3]);
        }
    }
}

// ---------------- main kernel ----------------
__global__ void __launch_bounds__(NTH, 2)
lstm_mma_kernel(const float* __restrict__ inseq,
                const float* __restrict__ fcW, const float* __restrict__ fcbp,
                float* __restrict__ out)
{
    extern __shared__ char sm[];
    const uint32_t sA = smem_u32(sm);
    float* tbl  = (float*)(sm + OFF_TBL);
    float* fcw  = (float*)(sm + OFF_FCW);
    float* fcb  = (float*)(sm + OFF_FCB);
    float* xdec = (float*)(sm + OFF_XD);

    const int tid = threadIdx.x;
    const int lane = tid & 31, w = tid >> 5;
    const int wm = w >> 2, wn = w & 3;
    const int m0 = 16 * wm;
    const int bm = blockIdx.x * ROWS;

    if (tid < 256) fcw[tid] = fcW[tid];
    if (tid < 2)   fcb[tid] = fcbp[tid];
    if (tid < 2 * ROWS)
        xdec[tid] = inseq[(size_t)(bm + (tid >> 1)) * 40 + 38 + (tid & 1)];
    for (int i = tid; i < 8192; i += NTH)         // zero A1 hi+lo (32KB)
        ((uint32_t*)(sm + OFF_A1H))[i] = 0u;
    __syncthreads();

    float c0[16], c1[16];
    #pragma unroll
    for (int i = 0; i < 16; i++) { c0[i] = 0.0f; c1[i] = 0.0f; }

    // staging -> A1 (de-interleave packed h into hi/lo, swizzle)
    auto copyS = [&](int koff) {
        #pragma unroll
        for (int i = 0; i < 2; i++) {
            const int u = tid + i * NTH;          // 0..511 A-units
            const int r = u >> 4, cu = u & 15;
            const uint4* Sp = (const uint4*)(sm + OFF_SP) + r * 32;
            const uint4 s0 = Sp[2 * cu], s1 = Sp[2 * cu + 1];
            uint4 hi, lo;
            hi.x = __byte_perm(s0.x, s0.y, 0x5410); lo.x = __byte_perm(s0.x, s0.y, 0x7632);
            hi.y = __byte_perm(s0.z, s0.w, 0x5410); lo.y = __byte_perm(s0.z, s0.w, 0x7632);
            hi.z = __byte_perm(s1.x, s1.y, 0x5410); lo.z = __byte_perm(s1.x, s1.y, 0x7632);
            hi.w = __byte_perm(s1.z, s1.w, 0x5410); lo.w = __byte_perm(s1.z, s1.w, 0x7632);
            const int dc = (koff + cu) ^ (r & 7);
            ((uint4*)(sm + OFF_A1H))[r * 32 + dc] = hi;
            ((uint4*)(sm + OFF_A1L))[r * 32 + dc] = lo;
        }
    };

    const int ra = m0 + (lane >> 2), rb = ra + 8;

    for (int t = 0; t < TTOT; t++) {
        const bool enc = t < TIN;
        if (t == 0 || t == TIN) {
            // stage this phase's bias/wx tables
            for (int i = tid; i < 2048; i += NTH) {
                const int seg = i >> 9, idx = i & 511;
                int srcoff;
                if      (seg == 0) srcoff = (enc ? 0 : 1024) + idx;
                else if (seg == 1) srcoff = (enc ? 512 : 1536) + idx;
                else if (seg == 2) srcoff = 2048 + (enc ? 0 : 1024) + idx;
                else               srcoff = 2560 + (enc ? 0 : 1024) + idx;
                tbl[i] = g_tbl[srcoff];
            }
            __syncthreads();
        }
        float xa0, xa1, xb0, xb1;
        if (enc) {
            const float2 xA = *(const float2*)(inseq + (size_t)(bm + ra) * 40 + 2 * t);
            const float2 xB = *(const float2*)(inseq + (size_t)(bm + rb) * 40 + 2 * t);
            xa0 = xA.x; xa1 = xA.y; xb0 = xB.x; xb1 = xB.y;
        } else {
            xa0 = xdec[ra * 2]; xa1 = xdec[ra * 2 + 1];
            xb0 = xdec[rb * 2]; xb1 = xdec[rb * 2 + 1];
        }
        // ---- layer 0 (K=128, reads A1 cols 0:128 = h0 old) ----
        gemm_layer<128>(sm, sA, g_wbuf + (enc ? 0 : 131072),
                        tbl, tbl + 1024, tbl + 1536, true,
                        xa0, xa1, xb0, xb1, c0, tid, lane, wn, m0);
        __syncthreads();
        copyS(0);                 // h0 new -> A1 cols 0:128
        // ---- layer 1 (K=256, reads [h0 new | h1 old]); first internal BAR publishes copyS
        gemm_layer<256>(sm, sA, g_wbuf + (enc ? 262144 : 524288),
                        tbl + 512, nullptr, nullptr, false,
                        0.0f, 0.0f, 0.0f, 0.0f, c1, tid, lane, wn, m0);
        __syncthreads();
        copyS(16);                // h1 new -> A1 cols 128:256
        if (!enc) {
            __syncthreads();      // publish copyS(16) for fc
            if (tid < 2 * ROWS) {
                const int r = tid >> 1, o = tid & 1;
                float a = fcb[o];
                #pragma unroll 4
                for (int c = 0; c < 16; c++) {
                    const int dc = (16 + c) ^ (r & 7);
                    const uint4 hq = ((const uint4*)(sm + OFF_A1H))[r * 32 + dc];
                    const uint4 lq = ((const uint4*)(sm + OFF_A1L))[r * 32 + dc];
                    const uint32_t hv[4] = {hq.x, hq.y, hq.z, hq.w};
                    const uint32_t lv[4] = {lq.x, lq.y, lq.z, lq.w};
                    #pragma unroll
                    for (int g = 0; g < 4; g++) {
                        const float h0f = __uint_as_float(hv[g] << 16) +
                                          __uint_as_float(lv[g] << 16);
                        const float h1f = __uint_as_float(hv[g] & 0xffff0000u) +
                                          __uint_as_float(lv[g] & 0xffff0000u);
                        a = fmaf(h0f, fcw[o * 128 + 8 * c + 2 * g], a);
                        a = fmaf(h1f, fcw[o * 128 + 8 * c + 2 * g + 1], a);
                    }
                }
                out[(size_t)(bm + r) * (TDEC * 2) + (t - TIN) * 2 + o] = a;
                xdec[tid] = a;
            }
            __syncthreads();      // xdec visible for next t
        }
    }
}

extern "C" void kernel_launch(void* const* d_in, const int* in_sizes, int n_in,
                              void* d_out, int out_size)
{
    (void)in_sizes; (void)n_in; (void)out_size;
    const float* inseq = (const float*)d_in[0];
    const float* eWih0 = (const float*)d_in[1];
    const float* eWhh0 = (const float*)d_in[2];
    const float* ebih0 = (const float*)d_in[3];
    const float* ebhh0 = (const float*)d_in[4];
    const float* eWih1 = (const float*)d_in[5];
    const float* eWhh1 = (const float*)d_in[6];
    const float* ebih1 = (const float*)d_in[7];
    const float* ebhh1 = (const float*)d_in[8];
    const float* dWih0 = (const float*)d_in[9];
    const float* dWhh0 = (const float*)d_in[10];
    const float* dbih0 = (const float*)d_in[11];
    const float* dbhh0 = (const float*)d_in[12];
    const float* dWih1 = (const float*)d_in[13];
    const float* dWhh1 = (const float*)d_in[14];
    const float* dbih1 = (const float*)d_in[15];
    const float* dbhh1 = (const float*)d_in[16];
    const float* fcW   = (const float*)d_in[17];
    const float* fcb   = (const float*)d_in[18];
    float* out = (float*)d_out;

    prep_weights<<<3072, 256>>>(eWhh0, dWhh0, eWih1, eWhh1, dWih1, dWhh1);
    prep_tables<<<16, 256>>>(ebih0, ebhh0, ebih1, ebhh1,
                             dbih0, dbhh0, dbih1, dbhh1, eWih0, dWih0);

    cudaFuncSetAttribute(lstm_mma_kernel,
                         cudaFuncAttributeMaxDynamicSharedMemorySize, SMEM_TOTAL);
    lstm_mma_kernel<<<32768 / ROWS, NTH, SMEM_TOTAL>>>(inseq, fcW, fcb, out);
}

// round 13
// speedup vs baseline: 4.6903x; 1.3343x over previous
#include <cuda_runtime.h>
#include <cuda_fp16.h>
#include <cstdint>

#define TIN  20
#define TDEC 45
#define TTOT 65
#define NTH  256
#define ROWS 32

// prepped fp16 weights: mats {eL0@0(16ch), dL0@65536, eL1@131072(32ch), dL1@262144}
// chunk (4096 halfs = 8KB): [n128][k32], chunk idx = pass*NCK + ck
__device__ __align__(256) __half g_wbuf[393216];
// prepped f32 tables: be0@0 be1@512 bd0@1024 bd1@1536 | wie0@2048 wie1@2560 wid0@3072 wid1@3584
__device__ __align__(256) float g_tbl[4096];

// smem layout (byte offsets):
// [0, 65536)  8 x 8KB A-state buffers: AB(reg,pp) = reg*32768 + pp*16384 (hi), +8192 (lo)
//             reg0 = h0, reg1 = h1; each 32 rows x 128 cols fp16, 256B/row, XOR-swizzled 16B units
#define OFF_WB  65536      // 3 x 8KB weight chunk triple buffer
#define OFF_TBL 90112      // staged: biasL0[512] biasL1[512] wx0[512] wx1[512]
#define OFF_FCW 98304      // 256 f32
#define OFF_FCB 99328
#define OFF_XD  99336      // 32 x 2 f32
#define SMEM_TOTAL 99840

#define AB(reg, pp) ((uint32_t)((reg) * 32768 + (pp) * 16384))

__device__ __forceinline__ uint32_t smem_u32(const void* p) {
    uint32_t a;
    asm("{ .reg .u64 t; cvta.to.shared.u64 t, %1; cvt.u32.u64 %0, t; }" : "=r"(a) : "l"(p));
    return a;
}
__device__ __forceinline__ void ldsm4(uint32_t* r, uint32_t a) {
    asm volatile("ldmatrix.sync.aligned.m8n8.x4.shared.b16 {%0,%1,%2,%3}, [%4];"
                 : "=r"(r[0]), "=r"(r[1]), "=r"(r[2]), "=r"(r[3]) : "r"(a));
}
__device__ __forceinline__ void mma16816(float* d, const uint32_t* a, uint32_t b0, uint32_t b1) {
    asm volatile("mma.sync.aligned.m16n8k16.row.col.f32.f16.f16.f32 "
                 "{%0,%1,%2,%3}, {%4,%5,%6,%7}, {%8,%9}, {%0,%1,%2,%3};"
                 : "+f"(d[0]), "+f"(d[1]), "+f"(d[2]), "+f"(d[3])
                 : "r"(a[0]), "r"(a[1]), "r"(a[2]), "r"(a[3]), "r"(b0), "r"(b1));
}
__device__ __forceinline__ void cpasync16(uint32_t dst, const void* src) {
    asm volatile("cp.async.cg.shared.global [%0], [%1], 16;" :: "r"(dst), "l"(src));
}
__device__ __forceinline__ float sigf(float x)   { return __fdividef(1.0f, 1.0f + __expf(-x)); }
__device__ __forceinline__ float tanhf_(float x) { return 2.0f * __fdividef(1.0f, 1.0f + __expf(-2.0f * x)) - 1.0f; }
__device__ __forceinline__ float h2lo(uint32_t w) {
    return __half2float(__ushort_as_half((unsigned short)(w & 0xffffu)));
}
__device__ __forceinline__ float h2hi(uint32_t w) {
    return __half2float(__ushort_as_half((unsigned short)(w >> 16)));
}

// ---------------- prep kernels ----------------
__global__ __launch_bounds__(256)
void prep_weights(const float* __restrict__ eWhh0, const float* __restrict__ dWhh0,
                  const float* __restrict__ eWih1, const float* __restrict__ eWhh1,
                  const float* __restrict__ dWih1, const float* __restrict__ dWhh1)
{
    int e = blockIdx.x * 256 + threadIdx.x;
    if (e >= 393216) return;
    int mat, base, K;
    if      (e < 65536)  { mat = 0; base = 0;      K = 128; }
    else if (e < 131072) { mat = 1; base = 65536;  K = 128; }
    else if (e < 262144) { mat = 2; base = 131072; K = 256; }
    else                 { mat = 3; base = 262144; K = 256; }
    int loc = e - base;
    int chunk = loc >> 12, rem = loc & 4095;
    int n = rem >> 5, k = rem & 31;
    int nck = K / 32;
    int p = chunk / nck, ck = chunk % nck;
    int col = p * 128 + n;
    int orig = (col & 3) * 128 + (col >> 2);    // gate g*128 + j
    int kg = ck * 32 + k;

    float wv;
    if      (mat == 0) wv = eWhh0[orig * 128 + kg];
    else if (mat == 1) wv = dWhh0[orig * 128 + kg];
    else {
        const float* Wi = (mat == 2) ? eWih1 : dWih1;
        const float* Wh = (mat == 2) ? eWhh1 : dWhh1;
        wv = (kg < 128) ? Wi[orig * 128 + kg] : Wh[orig * 128 + (kg - 128)];
    }
    g_wbuf[e] = __float2half_rn(wv);
}

__global__ __launch_bounds__(256)
void prep_tables(const float* __restrict__ ebih0, const float* __restrict__ ebhh0,
                 const float* __restrict__ ebih1, const float* __restrict__ ebhh1,
                 const float* __restrict__ dbih0, const float* __restrict__ dbhh0,
                 const float* __restrict__ dbih1, const float* __restrict__ dbhh1,
                 const float* __restrict__ eWih0, const float* __restrict__ dWih0)
{
    int i = blockIdx.x * 256 + threadIdx.x;
    if (i >= 4096) return;
    int col = i & 511;
    int orig = (col & 3) * 128 + (col >> 2);
    int seg = i >> 9;
    float v;
    switch (seg) {
        case 0: v = ebih0[orig] + ebhh0[orig]; break;
        case 1: v = ebih1[orig] + ebhh1[orig]; break;
        case 2: v = dbih0[orig] + dbhh0[orig]; break;
        case 3: v = dbih1[orig] + dbhh1[orig]; break;
        case 4: v = eWih0[2 * orig];     break;
        case 5: v = eWih0[2 * orig + 1]; break;
        case 6: v = dWih0[2 * orig];     break;
        default: v = dWih0[2 * orig + 1]; break;
    }
    g_tbl[i] = v;
}

// ---------------- one layer: 2-term fp16 GEMM + LSTM epilogue (direct A write) ----------------
// aB0: A byte-offset for k 0:127; aB1: for k 128:255 (L1 only). wT: write target (hi; lo=+8192).
template <int K>
__device__ __forceinline__ void gemm_layer(
    char* sm, uint32_t sA, const __half* __restrict__ wsrc,
    const float* __restrict__ bias, const float* __restrict__ wx0,
    const float* __restrict__ wx1, bool use_x,
    float xa0, float xa1, float xb0, float xb1,
    float* cst, int tid, int lane, int wn, int m0,
    uint32_t aB0, uint32_t aB1, uint32_t wT)
{
    constexpr int NCK = K / 32;          // k-chunks per pass
    constexpr int NCT = 4 * NCK;         // total chunks
    const int l8 = lane & 7;
    const int g2 = lane >> 3;
    const int khalf = (lane >> 4) & 1;
    const int rA = m0 + (lane & 15);

    auto issue = [&](int ci) {
        const __half* src = wsrc + (size_t)ci * 4096;
        const uint32_t dbase = sA + OFF_WB + (uint32_t)(ci % 3) * 8192u;
        #pragma unroll
        for (int i = 0; i < 2; i++) {
            const int u = tid + i * NTH;          // 0..511 16B units
            const int n = u >> 2, kc8 = u & 3;
            cpasync16(dbase + n * 64 + ((uint32_t)(kc8 ^ ((n >> 1) & 3)) << 4),
                      src + (size_t)u * 8);
        }
        asm volatile("cp.async.commit_group;" ::: "memory");
    };

    issue(0);
    issue(1);

    #pragma unroll 1
    for (int p = 0; p < 4; p++) {
        // accumulator init: bias (+ x-term for layer 0)
        float acc[4][4];
        #pragma unroll
        for (int nt = 0; nt < 4; nt++) {
            const int col0 = 128 * p + 32 * wn + 8 * nt + 2 * (lane & 3);
            const float b0 = bias[col0], b1 = bias[col0 + 1];
            if (use_x) {
                const float w00 = wx0[col0], w01 = wx0[col0 + 1];
                const float w10 = wx1[col0], w11 = wx1[col0 + 1];
                acc[nt][0] = fmaf(w10, xa1, fmaf(w00, xa0, b0));
                acc[nt][1] = fmaf(w11, xa1, fmaf(w01, xa0, b1));
                acc[nt][2] = fmaf(w10, xb1, fmaf(w00, xb0, b0));
                acc[nt][3] = fmaf(w11, xb1, fmaf(w01, xb0, b1));
            } else {
                acc[nt][0] = b0; acc[nt][1] = b1;
                acc[nt][2] = b0; acc[nt][3] = b1;
            }
        }

        #pragma unroll 1
        for (int ck = 0; ck < NCK; ck++) {
            const int ci = p * NCK + ck;
            if (ci == NCT - 1) asm volatile("cp.async.wait_group 0;" ::: "memory");
            else               asm volatile("cp.async.wait_group 1;" ::: "memory");
            __syncthreads();
            if (ci + 2 < NCT) issue(ci + 2);
            const uint32_t wb = sA + OFF_WB + (uint32_t)(ci % 3) * 8192u;
            const uint32_t aB = (K == 256 && ck >= NCK / 2) ? aB1 : aB0;
            const uint32_t arowH = sA + aB + (uint32_t)rA * 256u;
            #pragma unroll
            for (int ks = 0; ks < 2; ks++) {
                const uint32_t cu =
                    ((uint32_t)((4 * ck + 2 * ks + khalf) & 15)) ^ (uint32_t)l8;
                uint32_t ah[4], al[4];
                ldsm4(ah, arowH + (cu << 4));
                ldsm4(al, arowH + 8192u + (cu << 4));
                #pragma unroll
                for (int q = 0; q < 2; q++) {
                    const int n_row = 32 * wn + 16 * q + 8 * (g2 >> 1) + l8;
                    const int kc8v = 2 * ks + (g2 & 1);
                    const uint32_t off = (uint32_t)(n_row * 64) +
                        ((uint32_t)(kc8v ^ ((n_row >> 1) & 3)) << 4);
                    uint32_t bw[4];
                    ldsm4(bw, wb + off);
                    mma16816(acc[2 * q],     ah, bw[0], bw[1]);
                    mma16816(acc[2 * q],     al, bw[0], bw[1]);
                    mma16816(acc[2 * q + 1], ah, bw[2], bw[3]);
                    mma16816(acc[2 * q + 1], al, bw[2], bw[3]);
                }
            }
        }

        // epilogue pass p: gates -> (c,h); write h (fp16 hi/lo) directly to pong buffer
        const int odd = lane & 1;
        const int rowE = m0 + (lane >> 2) + (odd ? 8 : 0);
        uint32_t hi4[4], lo4[4];
        #pragma unroll
        for (int nt = 0; nt < 4; nt++) {
            const float e0 = __shfl_xor_sync(0xffffffffu, acc[nt][0], 1);
            const float e1 = __shfl_xor_sync(0xffffffffu, acc[nt][1], 1);
            const float e2 = __shfl_xor_sync(0xffffffffu, acc[nt][2], 1);
            const float e3 = __shfl_xor_sync(0xffffffffu, acc[nt][3], 1);
            float xi, xf, xg, xo;
            if (!odd) { xi = acc[nt][0]; xf = acc[nt][1]; xg = e0; xo = e1; }
            else      { xi = e2; xf = e3; xg = acc[nt][2]; xo = acc[nt][3]; }
            const float cn = fmaf(sigf(xf), cst[p * 4 + nt], sigf(xi) * tanhf_(xg));
            cst[p * 4 + nt] = cn;
            const float h = sigf(xo) * tanhf_(cn);
            const __half hh = __float2half_rn(h);
            const __half hl = __float2half_rn(h - __half2float(hh));
            const uint32_t v = (uint32_t)__half_as_ushort(hh) |
                               ((uint32_t)__half_as_ushort(hl) << 16);
            const uint32_t vx = __shfl_xor_sync(0xffffffffu, v, 2);
            hi4[nt] = __byte_perm(v, vx, 0x5410);
            lo4[nt] = __byte_perm(v, vx, 0x7632);
        }
        if ((lane & 2) == 0) {
            const uint32_t cu = ((uint32_t)(4 * p + wn)) ^ (uint32_t)(rowE & 7);
            char* wadr = sm + wT + rowE * 256 + (cu << 4);
            *(uint4*)wadr          = make_uint4(hi4[0], hi4[1], hi4[2], hi4[3]);
            *(uint4*)(wadr + 8192) = make_uint4(lo4[0], lo4[1], lo4[2], lo4[3]);
        }
    }
}

// ---------------- main kernel ----------------
__global__ void __launch_bounds__(NTH, 2)
lstm_mma_kernel(const float* __restrict__ inseq,
                const float* __restrict__ fcW, const float* __restrict__ fcbp,
                float* __restrict__ out)
{
    extern __shared__ char sm[];
    const uint32_t sA = smem_u32(sm);
    float* tbl  = (float*)(sm + OFF_TBL);
    float* fcw  = (float*)(sm + OFF_FCW);
    float* fcb  = (float*)(sm + OFF_FCB);
    float* xdec = (float*)(sm + OFF_XD);

    const int tid = threadIdx.x;
    const int lane = tid & 31, w = tid >> 5;
    const int wm = w >> 2, wn = w & 3;
    const int m0 = 16 * wm;
    const int bm = blockIdx.x * ROWS;

    if (tid < 256) fcw[tid] = fcW[tid];
    if (tid < 2)   fcb[tid] = fcbp[tid];
    if (tid < 2 * ROWS)
        xdec[tid] = inseq[(size_t)(bm + (tid >> 1)) * 40 + 38 + (tid & 1)];
    for (int i = tid; i < 16384; i += NTH)        // zero all 8 A buffers (64KB)
        ((uint32_t*)sm)[i] = 0u;
    __syncthreads();

    float c0[16], c1[16];
    #pragma unroll
    for (int i = 0; i < 16; i++) { c0[i] = 0.0f; c1[i] = 0.0f; }

    int cur0 = 0, cur1 = 0;
    const int ra = m0 + (lane >> 2), rb = ra + 8;

    for (int t = 0; t < TTOT; t++) {
        const bool enc = t < TIN;
        if (t == 0 || t == TIN) {
            for (int i = tid; i < 2048; i += NTH) {
                const int seg = i >> 9, idx = i & 511;
                int srcoff;
                if      (seg == 0) srcoff = (enc ? 0 : 1024) + idx;
                else if (seg == 1) srcoff = (enc ? 512 : 1536) + idx;
                else if (seg == 2) srcoff = 2048 + (enc ? 0 : 1024) + idx;
                else               srcoff = 2560 + (enc ? 0 : 1024) + idx;
                tbl[i] = g_tbl[srcoff];
            }
            __syncthreads();
        }
        float xa0, xa1, xb0, xb1;
        if (enc) {
            const float2 xA = *(const float2*)(inseq + (size_t)(bm + ra) * 40 + 2 * t);
            const float2 xB = *(const float2*)(inseq + (size_t)(bm + rb) * 40 + 2 * t);
            xa0 = xA.x; xa1 = xA.y; xb0 = xB.x; xb1 = xB.y;
        } else {
            xa0 = xdec[ra * 2]; xa1 = xdec[ra * 2 + 1];
            xb0 = xdec[rb * 2]; xb1 = xdec[rb * 2 + 1];
        }
        // ---- layer 0: reads h0[cur0], writes h0[cur0^1] ----
        gemm_layer<128>(sm, sA, g_wbuf + (enc ? 0 : 65536),
                        tbl, tbl + 1024, tbl + 1536, true,
                        xa0, xa1, xb0, xb1, c0, tid, lane, wn, m0,
                        AB(0, cur0), AB(0, cur0), AB(0, cur0 ^ 1));
        cur0 ^= 1;
        __syncthreads();   // WB reuse + h0-new visibility for L1
        // ---- layer 1: reads [h0 new | h1 old], writes h1[cur1^1] ----
        gemm_layer<256>(sm, sA, g_wbuf + (enc ? 131072 : 262144),
                        tbl + 512, nullptr, nullptr, false,
                        0.0f, 0.0f, 0.0f, 0.0f, c1, tid, lane, wn, m0,
                        AB(0, cur0), AB(1, cur1), AB(1, cur1 ^ 1));
        cur1 ^= 1;
        __syncthreads();   // WB reuse + h1-new visibility
        if (!enc) {
            if (tid < 2 * ROWS) {
                const int r = tid >> 1, o = tid & 1;
                const char* hB = sm + AB(1, cur1) + r * 256;
                float a = fcb[o];
                #pragma unroll 4
                for (int cu = 0; cu < 16; cu++) {
                    const uint32_t dc = ((uint32_t)cu) ^ (uint32_t)(r & 7);
                    const uint4 hq = *(const uint4*)(hB + (dc << 4));
                    const uint4 lq = *(const uint4*)(hB + 8192 + (dc << 4));
                    const uint32_t hv[4] = {hq.x, hq.y, hq.z, hq.w};
                    const uint32_t lv[4] = {lq.x, lq.y, lq.z, lq.w};
                    #pragma unroll
                    for (int g = 0; g < 4; g++) {
                        const float he = h2lo(hv[g]) + h2lo(lv[g]);
                        const float ho = h2hi(hv[g]) + h2hi(lv[g]);
                        a = fmaf(he, fcw[o * 128 + 8 * cu + 2 * g], a);
                        a = fmaf(ho, fcw[o * 128 + 8 * cu + 2 * g + 1], a);
                    }
                }
                out[(size_t)(bm + r) * (TDEC * 2) + (t - TIN) * 2 + o] = a;
                xdec[tid] = a;
            }
            __syncthreads();   // xdec visible for next step
        }
    }
}

extern "C" void kernel_launch(void* const* d_in, const int* in_sizes, int n_in,
                              void* d_out, int out_size)
{
    (void)in_sizes; (void)n_in; (void)out_size;
    const float* inseq = (const float*)d_in[0];
    const float* eWih0 = (const float*)d_in[1];
    const float* eWhh0 = (const float*)d_in[2];
    const float* ebih0 = (const float*)d_in[3];
    const float* ebhh0 = (const float*)d_in[4];
    const float* eWih1 = (const float*)d_in[5];
    const float* eWhh1 = (const float*)d_in[6];
    const float* ebih1 = (const float*)d_in[7];
    const float* ebhh1 = (const float*)d_in[8];
    const float* dWih0 = (const float*)d_in[9];
    const float* dWhh0 = (const float*)d_in[10];
    const float* dbih0 = (const float*)d_in[11];
    const float* dbhh0 = (const float*)d_in[12];
    const float* dWih1 = (const float*)d_in[13];
    const float* dWhh1 = (const float*)d_in[14];
    const float* dbih1 = (const float*)d_in[15];
    const float* dbhh1 = (const float*)d_in[16];
    const float* fcW   = (const float*)d_in[17];
    const float* fcb   = (const float*)d_in[18];
    float* out = (float*)d_out;

    prep_weights<<<1536, 256>>>(eWhh0, dWhh0, eWih1, eWhh1, dWih1, dWhh1);
    prep_tables<<<16, 256>>>(ebih0, ebhh0, ebih1, ebhh1,
                             dbih0, dbhh0, dbih1, dbhh1, eWih0, dWih0);

    cudaFuncSetAttribute(lstm_mma_kernel,
                         cudaFuncAttributeMaxDynamicSharedMemorySize, SMEM_TOTAL);
    lstm_mma_kernel<<<32768 / ROWS, NTH, SMEM_TOTAL>>>(inseq, fcW, fcb, out);
}

// round 14
// speedup vs baseline: 6.5199x; 1.3901x over previous
#include <cuda_runtime.h>
#include <cuda_fp16.h>
#include <cstdint>

#define TIN  20
#define TDEC 45
#define TTOT 65
#define NTH  256
#define ROWS 32

// prepped fp16 weights: mats {eL0@0(8ch), dL0@65536, eL1@131072(16ch), dL1@262144}
// chunk (8192 halfs = 16KB): [n128][k64], chunk idx = pass*NCK + ck, NCK=K/64
__device__ __align__(256) __half g_wbuf[393216];
// prepped f32 tables: be0@0 be1@512 bd0@1024 bd1@1536 | wie0@2048 wie1@2560 wid0@3072 wid1@3584
__device__ __align__(256) float g_tbl[4096];

// smem layout (byte offsets):
// [0, 32768)  4 x 8KB A-state buffers: AB(reg,pp) = reg*16384 + pp*8192
//             reg0=h0, reg1=h1; each 32 rows x 128 cols fp16 (256B/row), XOR-swizzled 16B units
#define OFF_WB  32768      // 3 x 16KB weight chunk triple buffer
#define OFF_TBL 81920      // staged: biasL0[512] biasL1[512] wx0[512] wx1[512]
#define OFF_FCW 90112      // 256 f32
#define OFF_FCB 91136
#define OFF_XD  91144      // 32 x 2 f32
#define SMEM_TOTAL 91648

#define AB(reg, pp) ((uint32_t)((reg) * 16384 + (pp) * 8192))

__device__ __forceinline__ uint32_t smem_u32(const void* p) {
    uint32_t a;
    asm("{ .reg .u64 t; cvta.to.shared.u64 t, %1; cvt.u32.u64 %0, t; }" : "=r"(a) : "l"(p));
    return a;
}
__device__ __forceinline__ void ldsm4(uint32_t* r, uint32_t a) {
    asm volatile("ldmatrix.sync.aligned.m8n8.x4.shared.b16 {%0,%1,%2,%3}, [%4];"
                 : "=r"(r[0]), "=r"(r[1]), "=r"(r[2]), "=r"(r[3]) : "r"(a));
}
__device__ __forceinline__ void mma16816(float* d, const uint32_t* a, uint32_t b0, uint32_t b1) {
    asm volatile("mma.sync.aligned.m16n8k16.row.col.f32.f16.f16.f32 "
                 "{%0,%1,%2,%3}, {%4,%5,%6,%7}, {%8,%9}, {%0,%1,%2,%3};"
                 : "+f"(d[0]), "+f"(d[1]), "+f"(d[2]), "+f"(d[3])
                 : "r"(a[0]), "r"(a[1]), "r"(a[2]), "r"(a[3]), "r"(b0), "r"(b1));
}
__device__ __forceinline__ void cpasync16(uint32_t dst, const void* src) {
    asm volatile("cp.async.cg.shared.global [%0], [%1], 16;" :: "r"(dst), "l"(src));
}
__device__ __forceinline__ float sigf(float x)   { return __fdividef(1.0f, 1.0f + __expf(-x)); }
__device__ __forceinline__ float tanhf_(float x) { return 2.0f * __fdividef(1.0f, 1.0f + __expf(-2.0f * x)) - 1.0f; }
__device__ __forceinline__ float h2lo(uint32_t w) {
    return __half2float(__ushort_as_half((unsigned short)(w & 0xffffu)));
}
__device__ __forceinline__ float h2hi(uint32_t w) {
    return __half2float(__ushort_as_half((unsigned short)(w >> 16)));
}

// ---------------- prep kernels ----------------
__global__ __launch_bounds__(256)
void prep_weights(const float* __restrict__ eWhh0, const float* __restrict__ dWhh0,
                  const float* __restrict__ eWih1, const float* __restrict__ eWhh1,
                  const float* __restrict__ dWih1, const float* __restrict__ dWhh1)
{
    int e = blockIdx.x * 256 + threadIdx.x;
    if (e >= 393216) return;
    int mat, base, K;
    if      (e < 65536)  { mat = 0; base = 0;      K = 128; }
    else if (e < 131072) { mat = 1; base = 65536;  K = 128; }
    else if (e < 262144) { mat = 2; base = 131072; K = 256; }
    else                 { mat = 3; base = 262144; K = 256; }
    int loc = e - base;
    int chunk = loc >> 13, rem = loc & 8191;
    int n = rem >> 6, k = rem & 63;
    int nck = K / 64;
    int p = chunk / nck, ck = chunk % nck;
    int col = p * 128 + n;
    int orig = (col & 3) * 128 + (col >> 2);    // gate g*128 + j
    int kg = ck * 64 + k;

    float wv;
    if      (mat == 0) wv = eWhh0[orig * 128 + kg];
    else if (mat == 1) wv = dWhh0[orig * 128 + kg];
    else {
        const float* Wi = (mat == 2) ? eWih1 : dWih1;
        const float* Wh = (mat == 2) ? eWhh1 : dWhh1;
        wv = (kg < 128) ? Wi[orig * 128 + kg] : Wh[orig * 128 + (kg - 128)];
    }
    g_wbuf[e] = __float2half_rn(wv);
}

__global__ __launch_bounds__(256)
void prep_tables(const float* __restrict__ ebih0, const float* __restrict__ ebhh0,
                 const float* __restrict__ ebih1, const float* __restrict__ ebhh1,
                 const float* __restrict__ dbih0, const float* __restrict__ dbhh0,
                 const float* __restrict__ dbih1, const float* __restrict__ dbhh1,
                 const float* __restrict__ eWih0, const float* __restrict__ dWih0)
{
    int i = blockIdx.x * 256 + threadIdx.x;
    if (i >= 4096) return;
    int col = i & 511;
    int orig = (col & 3) * 128 + (col >> 2);
    int seg = i >> 9;
    float v;
    switch (seg) {
        case 0: v = ebih0[orig] + ebhh0[orig]; break;
        case 1: v = ebih1[orig] + ebhh1[orig]; break;
        case 2: v = dbih0[orig] + dbhh0[orig]; break;
        case 3: v = dbih1[orig] + dbhh1[orig]; break;
        case 4: v = eWih0[2 * orig];     break;
        case 5: v = eWih0[2 * orig + 1]; break;
        case 6: v = dWih0[2 * orig];     break;
        default: v = dWih0[2 * orig + 1]; break;
    }
    g_tbl[i] = v;
}

// ---------------- one layer: single-term fp16 GEMM + LSTM epilogue ----------------
// aB0: A byte-offset for k 0:127; aB1: for k 128:255 (L1 only). wT: write target buffer.
template <int K>
__device__ __forceinline__ void gemm_layer(
    char* sm, uint32_t sA, const __half* __restrict__ wsrc,
    const float* __restrict__ bias, const float* __restrict__ wx0,
    const float* __restrict__ wx1, bool use_x,
    float xa0, float xa1, float xb0, float xb1,
    float* cst, int tid, int lane, int wn, int m0,
    uint32_t aB0, uint32_t aB1, uint32_t wT)
{
    constexpr int NCK = K / 64;          // k64-chunks per pass
    constexpr int NCT = 4 * NCK;         // total chunks
    const int l8 = lane & 7;
    const int g2 = lane >> 3;
    const int khalf = (lane >> 4) & 1;
    const int rA = m0 + (lane & 15);

    auto issue = [&](int ci) {
        const __half* src = wsrc + (size_t)ci * 8192;
        const uint32_t dbase = sA + OFF_WB + (uint32_t)(ci % 3) * 16384u;
        #pragma unroll
        for (int i = 0; i < 4; i++) {
            const int u = tid + i * NTH;          // 0..1023 16B units
            const int n = u >> 3, kc8 = u & 7;
            cpasync16(dbase + n * 128 + ((uint32_t)(kc8 ^ (n & 7)) << 4),
                      src + (size_t)u * 8);
        }
        asm volatile("cp.async.commit_group;" ::: "memory");
    };

    issue(0);
    issue(1);

    #pragma unroll 1
    for (int p = 0; p < 4; p++) {
        // accumulator init: bias (+ x-term for layer 0)
        float acc[4][4];
        #pragma unroll
        for (int nt = 0; nt < 4; nt++) {
            const int col0 = 128 * p + 32 * wn + 8 * nt + 2 * (lane & 3);
            const float b0 = bias[col0], b1 = bias[col0 + 1];
            if (use_x) {
                const float w00 = wx0[col0], w01 = wx0[col0 + 1];
                const float w10 = wx1[col0], w11 = wx1[col0 + 1];
                acc[nt][0] = fmaf(w10, xa1, fmaf(w00, xa0, b0));
                acc[nt][1] = fmaf(w11, xa1, fmaf(w01, xa0, b1));
                acc[nt][2] = fmaf(w10, xb1, fmaf(w00, xb0, b0));
                acc[nt][3] = fmaf(w11, xb1, fmaf(w01, xb0, b1));
            } else {
                acc[nt][0] = b0; acc[nt][1] = b1;
                acc[nt][2] = b0; acc[nt][3] = b1;
            }
        }

        #pragma unroll 1
        for (int ck = 0; ck < NCK; ck++) {
            const int ci = p * NCK + ck;
            if (ci == NCT - 1) asm volatile("cp.async.wait_group 0;" ::: "memory");
            else               asm volatile("cp.async.wait_group 1;" ::: "memory");
            __syncthreads();
            if (ci + 2 < NCT) issue(ci + 2);
            const uint32_t wb = sA + OFF_WB + (uint32_t)(ci % 3) * 16384u;
            const uint32_t aB = (K == 256 && ck >= NCK / 2) ? aB1 : aB0;
            const uint32_t arow = sA + aB + (uint32_t)rA * 256u;
            #pragma unroll
            for (int ks = 0; ks < 4; ks++) {
                const uint32_t cu =
                    ((uint32_t)((8 * ck + 2 * ks + khalf) & 15)) ^ (uint32_t)l8;
                uint32_t ah[4];
                ldsm4(ah, arow + (cu << 4));
                #pragma unroll
                for (int q = 0; q < 2; q++) {
                    const int n_row = 32 * wn + 16 * q + 8 * (g2 >> 1) + l8;
                    const int kc8v = 2 * ks + (g2 & 1);
                    const uint32_t off = (uint32_t)(n_row * 128) +
                        ((uint32_t)(kc8v ^ (n_row & 7)) << 4);
                    uint32_t bw[4];
                    ldsm4(bw, wb + off);
                    mma16816(acc[2 * q],     ah, bw[0], bw[1]);
                    mma16816(acc[2 * q + 1], ah, bw[2], bw[3]);
                }
            }
        }

        // epilogue pass p: gates -> (c,h); write h (single fp16) to pong buffer
        const int odd = lane & 1;
        const int rowE = m0 + (lane >> 2) + (odd ? 8 : 0);
        uint32_t hp4[4];
        #pragma unroll
        for (int nt = 0; nt < 4; nt++) {
            const float e0 = __shfl_xor_sync(0xffffffffu, acc[nt][0], 1);
            const float e1 = __shfl_xor_sync(0xffffffffu, acc[nt][1], 1);
            const float e2 = __shfl_xor_sync(0xffffffffu, acc[nt][2], 1);
            const float e3 = __shfl_xor_sync(0xffffffffu, acc[nt][3], 1);
            float xi, xf, xg, xo;
            if (!odd) { xi = acc[nt][0]; xf = acc[nt][1]; xg = e0; xo = e1; }
            else      { xi = e2; xf = e3; xg = acc[nt][2]; xo = acc[nt][3]; }
            const float cn = fmaf(sigf(xf), cst[p * 4 + nt], sigf(xi) * tanhf_(xg));
            cst[p * 4 + nt] = cn;
            const float h = sigf(xo) * tanhf_(cn);
            const uint32_t v = (uint32_t)__half_as_ushort(__float2half_rn(h));
            const uint32_t vx = __shfl_xor_sync(0xffffffffu, v, 2);
            hp4[nt] = (lane & 2) ? 0u : (v | (vx << 16));
        }
        if ((lane & 2) == 0) {
            const uint32_t cu = ((uint32_t)(4 * p + wn)) ^ (uint32_t)(rowE & 7);
            *(uint4*)(sm + wT + rowE * 256 + (cu << 4)) =
                make_uint4(hp4[0], hp4[1], hp4[2], hp4[3]);
        }
    }
}

// ---------------- main kernel ----------------
__global__ void __launch_bounds__(NTH, 2)
lstm_mma_kernel(const float* __restrict__ inseq,
                const float* __restrict__ fcW, const float* __restrict__ fcbp,
                float* __restrict__ out)
{
    extern __shared__ char sm[];
    const uint32_t sA = smem_u32(sm);
    float* tbl  = (float*)(sm + OFF_TBL);
    float* fcw  = (float*)(sm + OFF_FCW);
    float* fcb  = (float*)(sm + OFF_FCB);
    float* xdec = (float*)(sm + OFF_XD);

    const int tid = threadIdx.x;
    const int lane = tid & 31, w = tid >> 5;
    const int wm = w >> 2, wn = w & 3;
    const int m0 = 16 * wm;
    const int bm = blockIdx.x * ROWS;

    if (tid < 256) fcw[tid] = fcW[tid];
    if (tid < 2)   fcb[tid] = fcbp[tid];
    if (tid < 2 * ROWS)
        xdec[tid] = inseq[(size_t)(bm + (tid >> 1)) * 40 + 38 + (tid & 1)];
    for (int i = tid; i < 8192; i += NTH)         // zero all 4 A buffers (32KB)
        ((uint32_t*)sm)[i] = 0u;
    __syncthreads();

    float c0[16], c1[16];
    #pragma unroll
    for (int i = 0; i < 16; i++) { c0[i] = 0.0f; c1[i] = 0.0f; }

    int cur0 = 0, cur1 = 0;
    const int ra = m0 + (lane >> 2), rb = ra + 8;

    for (int t = 0; t < TTOT; t++) {
        const bool enc = t < TIN;
        if (t == 0 || t == TIN) {
            for (int i = tid; i < 2048; i += NTH) {
                const int seg = i >> 9, idx = i & 511;
                int srcoff;
                if      (seg == 0) srcoff = (enc ? 0 : 1024) + idx;
                else if (seg == 1) srcoff = (enc ? 512 : 1536) + idx;
                else if (seg == 2) srcoff = 2048 + (enc ? 0 : 1024) + idx;
                else               srcoff = 2560 + (enc ? 0 : 1024) + idx;
                tbl[i] = g_tbl[srcoff];
            }
            __syncthreads();
        }
        float xa0, xa1, xb0, xb1;
        if (enc) {
            const float2 xA = *(const float2*)(inseq + (size_t)(bm + ra) * 40 + 2 * t);
            const float2 xB = *(const float2*)(inseq + (size_t)(bm + rb) * 40 + 2 * t);
            xa0 = xA.x; xa1 = xA.y; xb0 = xB.x; xb1 = xB.y;
        } else {
            xa0 = xdec[ra * 2]; xa1 = xdec[ra * 2 + 1];
            xb0 = xdec[rb * 2]; xb1 = xdec[rb * 2 + 1];
        }
        // ---- layer 0: reads h0[cur0], writes h0[cur0^1] ----
        gemm_layer<128>(sm, sA, g_wbuf + (enc ? 0 : 65536),
                        tbl, tbl + 1024, tbl + 1536, true,
                        xa0, xa1, xb0, xb1, c0, tid, lane, wn, m0,
                        AB(0, cur0), AB(0, cur0), AB(0, cur0 ^ 1));
        cur0 ^= 1;
        __syncthreads();   // WB reuse + h0-new visibility for L1
        // ---- layer 1: reads [h0 new | h1 old], writes h1[cur1^1] ----
        gemm_layer<256>(sm, sA, g_wbuf + (enc ? 131072 : 262144),
                        tbl + 512, nullptr, nullptr, false,
                        0.0f, 0.0f, 0.0f, 0.0f, c1, tid, lane, wn, m0,
                        AB(0, cur0), AB(1, cur1), AB(1, cur1 ^ 1));
        cur1 ^= 1;
        __syncthreads();   // WB reuse + h1-new visibility
        if (!enc) {
            if (tid < 2 * ROWS) {
                const int r = tid >> 1, o = tid & 1;
                const char* hB = sm + AB(1, cur1) + r * 256;
                float a = fcb[o];
                #pragma unroll 4
                for (int cu = 0; cu < 16; cu++) {
                    const uint32_t dc = ((uint32_t)cu) ^ (uint32_t)(r & 7);
                    const uint4 hq = *(const uint4*)(hB + (dc << 4));
                    const uint32_t hv[4] = {hq.x, hq.y, hq.z, hq.w};
                    #pragma unroll
                    for (int g = 0; g < 4; g++) {
                        a = fmaf(h2lo(hv[g]), fcw[o * 128 + 8 * cu + 2 * g], a);
                        a = fmaf(h2hi(hv[g]), fcw[o * 128 + 8 * cu + 2 * g + 1], a);
                    }
                }
                out[(size_t)(bm + r) * (TDEC * 2) + (t - TIN) * 2 + o] = a;
                xdec[tid] = a;
            }
            __syncthreads();   // xdec visible for next step
        }
    }
}

extern "C" void kernel_launch(void* const* d_in, const int* in_sizes, int n_in,
                              void* d_out, int out_size)
{
    (void)in_sizes; (void)n_in; (void)out_size;
    const float* inseq = (const float*)d_in[0];
    const float* eWih0 = (const float*)d_in[1];
    const float* eWhh0 = (const float*)d_in[2];
    const float* ebih0 = (const float*)d_in[3];
    const float* ebhh0 = (const float*)d_in[4];
    const float* eWih1 = (const float*)d_in[5];
    const float* eWhh1 = (const float*)d_in[6];
    const float* ebih1 = (const float*)d_in[7];
    const float* ebhh1 = (const float*)d_in[8];
    const float* dWih0 = (const float*)d_in[9];
    const float* dWhh0 = (const float*)d_in[10];
    const float* dbih0 = (const float*)d_in[11];
    const float* dbhh0 = (const float*)d_in[12];
    const float* dWih1 = (const float*)d_in[13];
    const float* dWhh1 = (const float*)d_in[14];
    const float* dbih1 = (const float*)d_in[15];
    const float* dbhh1 = (const float*)d_in[16];
    const float* fcW   = (const float*)d_in[17];
    const float* fcb   = (const float*)d_in[18];
    float* out = (float*)d_out;

    prep_weights<<<1536, 256>>>(eWhh0, dWhh0, eWih1, eWhh1, dWih1, dWhh1);
    prep_tables<<<16, 256>>>(ebih0, ebhh0, ebih1, ebhh1,
                             dbih0, dbhh0, dbih1, dbhh1, eWih0, dWih0);

    cudaFuncSetAttribute(lstm_mma_kernel,
                         cudaFuncAttributeMaxDynamicSharedMemorySize, SMEM_TOTAL);
    lstm_mma_kernel<<<32768 / ROWS, NTH, SMEM_TOTAL>>>(inseq, fcW, fcb, out);
}

// round 15
// speedup vs baseline: 8.5567x; 1.3124x over previous
#include <cuda_runtime.h>
#include <cuda_fp16.h>
#include <cstdint>

#define TIN  20
#define TDEC 45
#define TTOT 65
#define NTH  128
#define ROWS 32

// prepped fp16 weights: mats {eL0@0(8ch), dL0@65536, eL1@131072(16ch), dL1@262144}
// chunk (8192 halfs = 16KB): [n128][k64], chunk idx = pass*NCK + ck, NCK=K/64
__device__ __align__(256) __half g_wbuf[393216];
// prepped f32 tables: be0@0 be1@512 bd0@1024 bd1@1536 | wie0@2048 wie1@2560 wid0@3072 wid1@3584
__device__ __align__(256) float g_tbl[4096];

// smem layout (byte offsets):
// [0, 32768)  4 x 8KB A-state buffers: AB(reg,pp) = reg*16384 + pp*8192
//             reg0=h0, reg1=h1; 32 rows x 128 cols fp16 (256B/row), XOR-swizzled 16B units
#define OFF_WB  32768      // 2 x 16KB weight chunk double buffer
#define OFF_TBL 65536      // staged: biasL0[512] biasL1[512] wx0[512] wx1[512]
#define OFF_FCW 73728      // 256 f32
#define OFF_FCB 74752      // 2 f32 (padded)
#define OFF_XD  74768      // 32 x 2 f32
#define SMEM_TOTAL 75264   // -> 3 CTAs/SM

#define AB(reg, pp) ((uint32_t)((reg) * 16384 + (pp) * 8192))

__device__ __forceinline__ uint32_t smem_u32(const void* p) {
    uint32_t a;
    asm("{ .reg .u64 t; cvta.to.shared.u64 t, %1; cvt.u32.u64 %0, t; }" : "=r"(a) : "l"(p));
    return a;
}
__device__ __forceinline__ void ldsm4(uint32_t* r, uint32_t a) {
    asm volatile("ldmatrix.sync.aligned.m8n8.x4.shared.b16 {%0,%1,%2,%3}, [%4];"
                 : "=r"(r[0]), "=r"(r[1]), "=r"(r[2]), "=r"(r[3]) : "r"(a));
}
__device__ __forceinline__ void mma16816(float* d, const uint32_t* a, uint32_t b0, uint32_t b1) {
    asm volatile("mma.sync.aligned.m16n8k16.row.col.f32.f16.f16.f32 "
                 "{%0,%1,%2,%3}, {%4,%5,%6,%7}, {%8,%9}, {%0,%1,%2,%3};"
                 : "+f"(d[0]), "+f"(d[1]), "+f"(d[2]), "+f"(d[3])
                 : "r"(a[0]), "r"(a[1]), "r"(a[2]), "r"(a[3]), "r"(b0), "r"(b1));
}
__device__ __forceinline__ void cpasync16(uint32_t dst, const void* src) {
    asm volatile("cp.async.cg.shared.global [%0], [%1], 16;" :: "r"(dst), "l"(src));
}
__device__ __forceinline__ float sigf(float x)   { return __fdividef(1.0f, 1.0f + __expf(-x)); }
__device__ __forceinline__ float tanhf_(float x) { return 2.0f * __fdividef(1.0f, 1.0f + __expf(-2.0f * x)) - 1.0f; }
__device__ __forceinline__ float h2lo(uint32_t w) {
    return __half2float(__ushort_as_half((unsigned short)(w & 0xffffu)));
}
__device__ __forceinline__ float h2hi(uint32_t w) {
    return __half2float(__ushort_as_half((unsigned short)(w >> 16)));
}

// ---------------- prep kernels (unchanged layout from R14) ----------------
__global__ __launch_bounds__(256)
void prep_weights(const float* __restrict__ eWhh0, const float* __restrict__ dWhh0,
                  const float* __restrict__ eWih1, const float* __restrict__ eWhh1,
                  const float* __restrict__ dWih1, const float* __restrict__ dWhh1)
{
    int e = blockIdx.x * 256 + threadIdx.x;
    if (e >= 393216) return;
    int mat, base, K;
    if      (e < 65536)  { mat = 0; base = 0;      K = 128; }
    else if (e < 131072) { mat = 1; base = 65536;  K = 128; }
    else if (e < 262144) { mat = 2; base = 131072; K = 256; }
    else                 { mat = 3; base = 262144; K = 256; }
    int loc = e - base;
    int chunk = loc >> 13, rem = loc & 8191;
    int n = rem >> 6, k = rem & 63;
    int nck = K / 64;
    int p = chunk / nck, ck = chunk % nck;
    int col = p * 128 + n;
    int orig = (col & 3) * 128 + (col >> 2);    // gate g*128 + j
    int kg = ck * 64 + k;

    float wv;
    if      (mat == 0) wv = eWhh0[orig * 128 + kg];
    else if (mat == 1) wv = dWhh0[orig * 128 + kg];
    else {
        const float* Wi = (mat == 2) ? eWih1 : dWih1;
        const float* Wh = (mat == 2) ? eWhh1 : dWhh1;
        wv = (kg < 128) ? Wi[orig * 128 + kg] : Wh[orig * 128 + (kg - 128)];
    }
    g_wbuf[e] = __float2half_rn(wv);
}

__global__ __launch_bounds__(256)
void prep_tables(const float* __restrict__ ebih0, const float* __restrict__ ebhh0,
                 const float* __restrict__ ebih1, const float* __restrict__ ebhh1,
                 const float* __restrict__ dbih0, const float* __restrict__ dbhh0,
                 const float* __restrict__ dbih1, const float* __restrict__ dbhh1,
                 const float* __restrict__ eWih0, const float* __restrict__ dWih0)
{
    int i = blockIdx.x * 256 + threadIdx.x;
    if (i >= 4096) return;
    int col = i & 511;
    int orig = (col & 3) * 128 + (col >> 2);
    int seg = i >> 9;
    float v;
    switch (seg) {
        case 0: v = ebih0[orig] + ebhh0[orig]; break;
        case 1: v = ebih1[orig] + ebhh1[orig]; break;
        case 2: v = dbih0[orig] + dbhh0[orig]; break;
        case 3: v = dbih1[orig] + dbhh1[orig]; break;
        case 4: v = eWih0[2 * orig];     break;
        case 5: v = eWih0[2 * orig + 1]; break;
        case 6: v = dWih0[2 * orig];     break;
        default: v = dWih0[2 * orig + 1]; break;
    }
    g_tbl[i] = v;
}

// ---------------- one layer: warp m32n32, B-frag reuse, reg-resident c-state ----------------
// aB0: A byte-offset for k 0:127; aB1: for k 128:255 (L1 only). wT: write target buffer.
// xs0/xs1: per-thread layer-0 inputs for row slots {16mi + ra, 16mi + ra + 8}.
template <int K>
__device__ __forceinline__ void gemm_layer(
    char* sm, uint32_t sA, const __half* __restrict__ wsrc,
    const float* __restrict__ bias, const float* __restrict__ wx0,
    const float* __restrict__ wx1, bool use_x,
    const float* xs0, const float* xs1,
    float* cst, int tid, int lane, int wn,
    uint32_t aB0, uint32_t aB1, uint32_t wT)
{
    constexpr int NCK = K / 64;          // k64-chunks per pass
    constexpr int NCT = 4 * NCK;         // total chunks
    const int l8 = lane & 7;
    const int g2 = lane >> 3;
    const int khalf = (lane >> 4) & 1;

    auto issue = [&](int ci) {
        const __half* src = wsrc + (size_t)ci * 8192;
        const uint32_t dbase = sA + OFF_WB + (uint32_t)(ci & 1) * 16384u;
        #pragma unroll
        for (int i = 0; i < 8; i++) {
            const int u = tid + i * NTH;          // 0..1023 16B units
            const int n = u >> 3, kc8 = u & 7;
            cpasync16(dbase + n * 128 + ((uint32_t)(kc8 ^ (n & 7)) << 4),
                      src + (size_t)u * 8);
        }
        asm volatile("cp.async.commit_group;" ::: "memory");
    };

    issue(0);

    #pragma unroll
    for (int p = 0; p < 4; p++) {
        // accumulator init: bias (+ x-term for layer 0)
        float acc[2][4][4];
        #pragma unroll
        for (int nt = 0; nt < 4; nt++) {
            const int col0 = 128 * p + 32 * wn + 8 * nt + 2 * (lane & 3);
            const float b0 = bias[col0], b1 = bias[col0 + 1];
            #pragma unroll
            for (int mi = 0; mi < 2; mi++) {
                if (use_x) {
                    const float w00 = wx0[col0], w01 = wx0[col0 + 1];
                    const float w10 = wx1[col0], w11 = wx1[col0 + 1];
                    acc[mi][nt][0] = fmaf(w10, xs1[2 * mi],     fmaf(w00, xs0[2 * mi],     b0));
                    acc[mi][nt][1] = fmaf(w11, xs1[2 * mi],     fmaf(w01, xs0[2 * mi],     b1));
                    acc[mi][nt][2] = fmaf(w10, xs1[2 * mi + 1], fmaf(w00, xs0[2 * mi + 1], b0));
                    acc[mi][nt][3] = fmaf(w11, xs1[2 * mi + 1], fmaf(w01, xs0[2 * mi + 1], b1));
                } else {
                    acc[mi][nt][0] = b0; acc[mi][nt][1] = b1;
                    acc[mi][nt][2] = b0; acc[mi][nt][3] = b1;
                }
            }
        }

        #pragma unroll 1
        for (int ck = 0; ck < NCK; ck++) {
            const int ci = p * NCK + ck;
            asm volatile("cp.async.wait_group 0;" ::: "memory");
            __syncthreads();                 // chunk ci visible; ci-1 fully consumed
            if (ci + 1 < NCT) issue(ci + 1); // safe overwrite; overlaps compute of ci
            const uint32_t wb = sA + OFF_WB + (uint32_t)(ci & 1) * 16384u;
            const uint32_t aB = (K == 256 && ck >= NCK / 2) ? aB1 : aB0;
            const uint32_t arA = sA + aB + (uint32_t)(lane & 15) * 256u;
            #pragma unroll
            for (int ks = 0; ks < 4; ks++) {
                const uint32_t cu =
                    ((uint32_t)((8 * ck + 2 * ks + khalf) & 15)) ^ (uint32_t)l8;
                uint32_t a0[4], a1[4];
                ldsm4(a0, arA + (cu << 4));           // rows 0..15
                ldsm4(a1, arA + 4096u + (cu << 4));   // rows 16..31
                #pragma unroll
                for (int q = 0; q < 2; q++) {
                    const int n_row = 32 * wn + 16 * q + 8 * (g2 >> 1) + l8;
                    const int kc8v = 2 * ks + (g2 & 1);
                    const uint32_t off = (uint32_t)(n_row * 128) +
                        ((uint32_t)(kc8v ^ (n_row & 7)) << 4);
                    uint32_t bw[4];
                    ldsm4(bw, wb + off);              // loaded once, used by both mi
                    mma16816(acc[0][2 * q],     a0, bw[0], bw[1]);
                    mma16816(acc[0][2 * q + 1], a0, bw[2], bw[3]);
                    mma16816(acc[1][2 * q],     a1, bw[0], bw[1]);
                    mma16816(acc[1][2 * q + 1], a1, bw[2], bw[3]);
                }
            }
        }

        // epilogue pass p: gates -> (c,h); write h (fp16) to pong buffer
        const int odd = lane & 1;
        #pragma unroll
        for (int mi = 0; mi < 2; mi++) {
            const int rowE = 16 * mi + (lane >> 2) + (odd ? 8 : 0);
            uint32_t hp4[4];
            #pragma unroll
            for (int nt = 0; nt < 4; nt++) {
                const float e0 = __shfl_xor_sync(0xffffffffu, acc[mi][nt][0], 1);
                const float e1 = __shfl_xor_sync(0xffffffffu, acc[mi][nt][1], 1);
                const float e2 = __shfl_xor_sync(0xffffffffu, acc[mi][nt][2], 1);
                const float e3 = __shfl_xor_sync(0xffffffffu, acc[mi][nt][3], 1);
                float xi, xf, xg, xo;
                if (!odd) { xi = acc[mi][nt][0]; xf = acc[mi][nt][1]; xg = e0; xo = e1; }
                else      { xi = e2; xf = e3; xg = acc[mi][nt][2]; xo = acc[mi][nt][3]; }
                const int cidx = (2 * p + mi) * 4 + nt;      // compile-time after unroll
                const float cn = fmaf(sigf(xf), cst[cidx], sigf(xi) * tanhf_(xg));
                cst[cidx] = cn;
                const float h = sigf(xo) * tanhf_(cn);
                const uint32_t v = (uint32_t)__half_as_ushort(__float2half_rn(h));
                const uint32_t vx = __shfl_xor_sync(0xffffffffu, v, 2);
                hp4[nt] = v | (vx << 16);
            }
            if ((lane & 2) == 0) {
                const uint32_t cuw = ((uint32_t)(4 * p + wn)) ^ (uint32_t)(rowE & 7);
                *(uint4*)(sm + wT + rowE * 256 + (cuw << 4)) =
                    make_uint4(hp4[0], hp4[1], hp4[2], hp4[3]);
            }
        }
    }
}

// ---------------- main kernel ----------------
__global__ void __launch_bounds__(NTH, 3)
lstm_mma_kernel(const float* __restrict__ inseq,
                const float* __restrict__ fcW, const float* __restrict__ fcbp,
                float* __restrict__ out)
{
    extern __shared__ char sm[];
    const uint32_t sA = smem_u32(sm);
    float* tbl  = (float*)(sm + OFF_TBL);
    float* fcw  = (float*)(sm + OFF_FCW);
    float* fcb  = (float*)(sm + OFF_FCB);
    float* xdec = (float*)(sm + OFF_XD);

    const int tid = threadIdx.x;
    const int lane = tid & 31, wn = tid >> 5;   // 4 warps, pure n-split
    const int bm = blockIdx.x * ROWS;
    const int ra = lane >> 2;

    for (int i = tid; i < 256; i += NTH) fcw[i] = fcW[i];
    if (tid < 2) fcb[tid] = fcbp[tid];
    if (tid < 2 * ROWS)
        xdec[tid] = inseq[(size_t)(bm + (tid >> 1)) * 40 + 38 + (tid & 1)];
    for (int i = tid; i < 8192; i += NTH)       // zero all 4 A buffers (32KB)
        ((uint32_t*)sm)[i] = 0u;
    __syncthreads();

    float c0[32], c1[32];
    #pragma unroll
    for (int i = 0; i < 32; i++) { c0[i] = 0.0f; c1[i] = 0.0f; }

    int cur0 = 0, cur1 = 0;
    const int r4[4] = { ra, ra + 8, ra + 16, ra + 24 };   // row slots (mi,half)

    for (int t = 0; t < TTOT; t++) {
        const bool enc = t < TIN;
        if (t == 0 || t == TIN) {
            for (int i = tid; i < 2048; i += NTH) {
                const int seg = i >> 9, idx = i & 511;
                int srcoff;
                if      (seg == 0) srcoff = (enc ? 0 : 1024) + idx;
                else if (seg == 1) srcoff = (enc ? 512 : 1536) + idx;
                else if (seg == 2) srcoff = 2048 + (enc ? 0 : 1024) + idx;
                else               srcoff = 2560 + (enc ? 0 : 1024) + idx;
                tbl[i] = g_tbl[srcoff];
            }
            __syncthreads();
        }
        float xs0[4], xs1[4];
        #pragma unroll
        for (int g = 0; g < 4; g++) {
            if (enc) {
                const float2 xv =
                    *(const float2*)(inseq + (size_t)(bm + r4[g]) * 40 + 2 * t);
                xs0[g] = xv.x; xs1[g] = xv.y;
            } else {
                xs0[g] = xdec[r4[g] * 2];
                xs1[g] = xdec[r4[g] * 2 + 1];
            }
        }
        // ---- layer 0: reads h0[cur0], writes h0[cur0^1] ----
        gemm_layer<128>(sm, sA, g_wbuf + (enc ? 0 : 65536),
                        tbl, tbl + 1024, tbl + 1536, true, xs0, xs1,
                        c0, tid, lane, wn,
                        AB(0, cur0), AB(0, cur0), AB(0, cur0 ^ 1));
        cur0 ^= 1;
        __syncthreads();   // WB reuse + h0-new visibility for L1
        // ---- layer 1: reads [h0 new | h1 old], writes h1[cur1^1] ----
        gemm_layer<256>(sm, sA, g_wbuf + (enc ? 131072 : 262144),
                        tbl + 512, nullptr, nullptr, false, xs0, xs1,
                        c1, tid, lane, wn,
                        AB(0, cur0), AB(1, cur1), AB(1, cur1 ^ 1));
        cur1 ^= 1;
        __syncthreads();   // WB reuse + h1-new visibility
        if (!enc) {
            if (tid < 2 * ROWS) {
                const int r = tid >> 1, o = tid & 1;
                const char* hB = sm + AB(1, cur1) + r * 256;
                float a = fcb[o];
                #pragma unroll 4
                for (int cu = 0; cu < 16; cu++) {
                    const uint32_t dc = ((uint32_t)cu) ^ (uint32_t)(r & 7);
                    const uint4 hq = *(const uint4*)(hB + (dc << 4));
                    const uint32_t hv[4] = {hq.x, hq.y, hq.z, hq.w};
                    #pragma unroll
                    for (int g = 0; g < 4; g++) {
                        a = fmaf(h2lo(hv[g]), fcw[o * 128 + 8 * cu + 2 * g], a);
                        a = fmaf(h2hi(hv[g]), fcw[o * 128 + 8 * cu + 2 * g + 1], a);
                    }
                }
                out[(size_t)(bm + r) * (TDEC * 2) + (t - TIN) * 2 + o] = a;
                xdec[tid] = a;
            }
            __syncthreads();   // xdec visible for next step
        }
    }
}

extern "C" void kernel_launch(void* const* d_in, const int* in_sizes, int n_in,
                              void* d_out, int out_size)
{
    (void)in_sizes; (void)n_in; (void)out_size;
    const float* inseq = (const float*)d_in[0];
    const float* eWih0 = (const float*)d_in[1];
    const float* eWhh0 = (const float*)d_in[2];
    const float* ebih0 = (const float*)d_in[3];
    const float* ebhh0 = (const float*)d_in[4];
    const float* eWih1 = (const float*)d_in[5];
    const float* eWhh1 = (const float*)d_in[6];
    const float* ebih1 = (const float*)d_in[7];
    const float* ebhh1 = (const float*)d_in[8];
    const float* dWih0 = (const float*)d_in[9];
    const float* dWhh0 = (const float*)d_in[10];
    const float* dbih0 = (const float*)d_in[11];
    const float* dbhh0 = (const float*)d_in[12];
    const float* dWih1 = (const float*)d_in[13];
    const float* dWhh1 = (const float*)d_in[14];
    const float* dbih1 = (const float*)d_in[15];
    const float* dbhh1 = (const float*)d_in[16];
    const float* fcW   = (const float*)d_in[17];
    const float* fcb   = (const float*)d_in[18];
    float* out = (float*)d_out;

    prep_weights<<<1536, 256>>>(eWhh0, dWhh0, eWih1, eWhh1, dWih1, dWhh1);
    prep_tables<<<16, 256>>>(ebih0, ebhh0, ebih1, ebhh1,
                             dbih0, dbhh0, dbih1, dbhh1, eWih0, dWih0);

    cudaFuncSetAttribute(lstm_mma_kernel,
                         cudaFuncAttributeMaxDynamicSharedMemorySize, SMEM_TOTAL);
    lstm_mma_kernel<<<32768 / ROWS, NTH, SMEM_TOTAL>>>(inseq, fcW, fcb, out);
}

// round 16
// speedup vs baseline: 8.9477x; 1.0457x over previous
#include <cuda_runtime.h>
#include <cuda_fp16.h>
#include <cstdint>

#define TIN  20
#define TDEC 45
#define TTOT 65
#define NTH  128
#define ROWS 32

// prepped fp16 weights in mma FRAGMENT order.
// u32 units: mats {eL0@0(8ch), dL0@32768, eL1@65536(16ch), dL1@131072} (u32 idx)
// chunk (4096 u32 = 16KB): [wn 0..3][i 0..7][lane 0..31][v 0..3]
//   i = 2*j + khalf  (j = n8 block 0..3, khalf = k32 half of the k64 chunk)
//   frag u32 (j, k8=4*khalf+v), lane l: halves B[col=128p+32wn+8j+l/4][k=64ck+8*k8+2*(l%4)+{0,1}]
__device__ __align__(256) __half g_wbuf[393216];
// prepped f32 tables: be0@0 be1@512 bd0@1024 bd1@1536 | wie0@2048 wie1@2560 wid0@3072 wid1@3584
__device__ __align__(256) float g_tbl[4096];

// smem layout (byte offsets):
// [0, 32768)  4 x 8KB A-state buffers: AB(reg,pp) = reg*16384 + pp*8192
//             reg0=h0, reg1=h1; 32 rows x 128 cols fp16 (256B/row), XOR-swizzled 16B units
#define OFF_TBL 32768      // staged: biasL0[512] biasL1[512] wx0[512] wx1[512]
#define OFF_FCW 40960      // 256 f32
#define OFF_FCB 41984      // 2 f32 (padded)
#define OFF_XD  42000      // 32 x 2 f32
#define SMEM_TOTAL 42496

#define AB(reg, pp) ((uint32_t)((reg) * 16384 + (pp) * 8192))

__device__ __forceinline__ uint32_t smem_u32(const void* p) {
    uint32_t a;
    asm("{ .reg .u64 t; cvta.to.shared.u64 t, %1; cvt.u32.u64 %0, t; }" : "=r"(a) : "l"(p));
    return a;
}
__device__ __forceinline__ void ldsm4(uint32_t* r, uint32_t a) {
    asm volatile("ldmatrix.sync.aligned.m8n8.x4.shared.b16 {%0,%1,%2,%3}, [%4];"
                 : "=r"(r[0]), "=r"(r[1]), "=r"(r[2]), "=r"(r[3]) : "r"(a));
}
__device__ __forceinline__ void mma16816(float* d, const uint32_t* a, uint32_t b0, uint32_t b1) {
    asm volatile("mma.sync.aligned.m16n8k16.row.col.f32.f16.f16.f32 "
                 "{%0,%1,%2,%3}, {%4,%5,%6,%7}, {%8,%9}, {%0,%1,%2,%3};"
                 : "+f"(d[0]), "+f"(d[1]), "+f"(d[2]), "+f"(d[3])
                 : "r"(a[0]), "r"(a[1]), "r"(a[2]), "r"(a[3]), "r"(b0), "r"(b1));
}
__device__ __forceinline__ float sigf(float x)   { return __fdividef(1.0f, 1.0f + __expf(-x)); }
__device__ __forceinline__ float tanhf_(float x) { return 2.0f * __fdividef(1.0f, 1.0f + __expf(-2.0f * x)) - 1.0f; }
__device__ __forceinline__ float h2lo(uint32_t w) {
    return __half2float(__ushort_as_half((unsigned short)(w & 0xffffu)));
}
__device__ __forceinline__ float h2hi(uint32_t w) {
    return __half2float(__ushort_as_half((unsigned short)(w >> 16)));
}

// ---------------- prep: weights -> fragment-ordered fp16 ----------------
__global__ __launch_bounds__(256)
void prep_weights(const float* __restrict__ eWhh0, const float* __restrict__ dWhh0,
                  const float* __restrict__ eWih1, const float* __restrict__ eWhh1,
                  const float* __restrict__ dWih1, const float* __restrict__ dWhh1)
{
    int e = blockIdx.x * 256 + threadIdx.x;       // u32 index
    if (e >= 196608) return;
    int mat, base, NCK;
    if      (e < 32768)  { mat = 0; base = 0;      NCK = 2; }
    else if (e < 65536)  { mat = 1; base = 32768;  NCK = 2; }
    else if (e < 131072) { mat = 2; base = 65536;  NCK = 4; }
    else                 { mat = 3; base = 131072; NCK = 4; }
    int loc = e - base;
    int ci = loc >> 12, w = loc & 4095;
    int wn = w >> 10, r = w & 1023;
    int i = r >> 7, l = (r >> 2) & 31, v = r & 3;
    int j = i >> 1, khalf = i & 1;
    int k8 = 4 * khalf + v;
    int np = 32 * wn + 8 * j + (l >> 2);
    int kc = 8 * k8 + 2 * (l & 3);
    int p = ci / NCK, ck = ci % NCK;
    int col = 128 * p + np;
    int orig = (col & 3) * 128 + (col >> 2);      // gate g*128 + j
    int kg = 64 * ck + kc;

    float w0, w1;
    if (mat == 0)      { w0 = eWhh0[orig * 128 + kg]; w1 = eWhh0[orig * 128 + kg + 1]; }
    else if (mat == 1) { w0 = dWhh0[orig * 128 + kg]; w1 = dWhh0[orig * 128 + kg + 1]; }
    else {
        const float* Wi = (mat == 2) ? eWih1 : dWih1;
        const float* Wh = (mat == 2) ? eWhh1 : dWhh1;
        w0 = (kg < 128)     ? Wi[orig * 128 + kg]       : Wh[orig * 128 + (kg - 128)];
        w1 = (kg + 1 < 128) ? Wi[orig * 128 + kg + 1]   : Wh[orig * 128 + (kg + 1 - 128)];
    }
    const uint32_t pk = (uint32_t)__half_as_ushort(__float2half_rn(w0)) |
                        ((uint32_t)__half_as_ushort(__float2half_rn(w1)) << 16);
    ((uint32_t*)g_wbuf)[e] = pk;
}

__global__ __launch_bounds__(256)
void prep_tables(const float* __restrict__ ebih0, const float* __restrict__ ebhh0,
                 const float* __restrict__ ebih1, const float* __restrict__ ebhh1,
                 const float* __restrict__ dbih0, const float* __restrict__ dbhh0,
                 const float* __restrict__ dbih1, const float* __restrict__ dbhh1,
                 const float* __restrict__ eWih0, const float* __restrict__ dWih0)
{
    int i = blockIdx.x * 256 + threadIdx.x;
    if (i >= 4096) return;
    int col = i & 511;
    int orig = (col & 3) * 128 + (col >> 2);
    int seg = i >> 9;
    float v;
    switch (seg) {
        case 0: v = ebih0[orig] + ebhh0[orig]; break;
        case 1: v = ebih1[orig] + ebhh1[orig]; break;
        case 2: v = dbih0[orig] + dbhh0[orig]; break;
        case 3: v = dbih1[orig] + dbhh1[orig]; break;
        case 4: v = eWih0[2 * orig];     break;
        case 5: v = eWih0[2 * orig + 1]; break;
        case 6: v = dWih0[2 * orig];     break;
        default: v = dWih0[2 * orig + 1]; break;
    }
    g_tbl[i] = v;
}

// ---------------- one layer: B via LDG fragments, A via ldsm, no inner barriers ----------------
template <int K>
__device__ __forceinline__ void gemm_layer(
    char* sm, uint32_t sA, const uint4* __restrict__ wmat,
    const float* __restrict__ bias, const float* __restrict__ wx0,
    const float* __restrict__ wx1, bool use_x,
    const float* xs0, const float* xs1,
    float* cst, int lane, int wn,
    uint32_t aB0, uint32_t aB1, uint32_t wT)
{
    constexpr int NCK = K / 64;          // k64-chunks per pass
    constexpr int NCT = 4 * NCK;         // total chunks
    constexpr int H = 2 * NCT;           // k32 halves
    const int l8 = lane & 7;
    const int lkh = (lane >> 4) & 1;
    const uint4* wl = wmat + wn * 256 + lane;

    uint4 cur[4], nxt[4];
    auto ldB = [&](uint4 q[4], int h) {
        const uint4* bp = wl + (size_t)(h >> 1) * 1024 + (h & 1) * 32;
        q[0] = __ldg(bp);
        q[1] = __ldg(bp + 64);
        q[2] = __ldg(bp + 128);
        q[3] = __ldg(bp + 192);
    };
    ldB(cur, 0);
    ldB(nxt, 1);

    #pragma unroll
    for (int p = 0; p < 4; p++) {
        // accumulator init: bias (+ x-term for layer 0)
        float acc[2][4][4];
        #pragma unroll
        for (int nt = 0; nt < 4; nt++) {
            const int col0 = 128 * p + 32 * wn + 8 * nt + 2 * (lane & 3);
            const float b0 = bias[col0], b1 = bias[col0 + 1];
            #pragma unroll
            for (int mi = 0; mi < 2; mi++) {
                if (use_x) {
                    const float w00 = wx0[col0], w01 = wx0[col0 + 1];
                    const float w10 = wx1[col0], w11 = wx1[col0 + 1];
                    acc[mi][nt][0] = fmaf(w10, xs1[2 * mi],     fmaf(w00, xs0[2 * mi],     b0));
                    acc[mi][nt][1] = fmaf(w11, xs1[2 * mi],     fmaf(w01, xs0[2 * mi],     b1));
                    acc[mi][nt][2] = fmaf(w10, xs1[2 * mi + 1], fmaf(w00, xs0[2 * mi + 1], b0));
                    acc[mi][nt][3] = fmaf(w11, xs1[2 * mi + 1], fmaf(w01, xs0[2 * mi + 1], b1));
                } else {
                    acc[mi][nt][0] = b0; acc[mi][nt][1] = b1;
                    acc[mi][nt][2] = b0; acc[mi][nt][3] = b1;
                }
            }
        }

        #pragma unroll
        for (int ck = 0; ck < NCK; ck++) {
            const int h0 = (p * NCK + ck) * 2;
            const uint32_t aB = (K == 256 && ck >= NCK / 2) ? aB1 : aB0;
            const uint32_t arA = sA + aB + (uint32_t)(lane & 15) * 256u;
            // ---- half 0 (cur): ks = 0,1 ----
            #pragma unroll
            for (int s = 0; s < 2; s++) {
                const uint32_t cu =
                    ((uint32_t)((8 * ck + 2 * s + lkh) & 15)) ^ (uint32_t)l8;
                uint32_t a0[4], a1[4];
                ldsm4(a0, arA + (cu << 4));
                ldsm4(a1, arA + 4096u + (cu << 4));
                #pragma unroll
                for (int j = 0; j < 4; j++) {
                    const uint32_t b0 = s ? cur[j].z : cur[j].x;
                    const uint32_t b1 = s ? cur[j].w : cur[j].y;
                    mma16816(acc[0][j], a0, b0, b1);
                    mma16816(acc[1][j], a1, b0, b1);
                }
            }
            if (h0 + 2 < H) ldB(cur, h0 + 2);
            // ---- half 1 (nxt): ks = 2,3 ----
            #pragma unroll
            for (int s = 0; s < 2; s++) {
                const uint32_t cu =
                    ((uint32_t)((8 * ck + 4 + 2 * s + lkh) & 15)) ^ (uint32_t)l8;
                uint32_t a0[4], a1[4];
                ldsm4(a0, arA + (cu << 4));
                ldsm4(a1, arA + 4096u + (cu << 4));
                #pragma unroll
                for (int j = 0; j < 4; j++) {
                    const uint32_t b0 = s ? nxt[j].z : nxt[j].x;
                    const uint32_t b1 = s ? nxt[j].w : nxt[j].y;
                    mma16816(acc[0][j], a0, b0, b1);
                    mma16816(acc[1][j], a1, b0, b1);
                }
            }
            if (h0 + 3 < H) ldB(nxt, h0 + 3);
        }

        // epilogue pass p: gates -> (c,h); write h (fp16) to pong buffer
        const int odd = lane & 1;
        #pragma unroll
        for (int mi = 0; mi < 2; mi++) {
            const int rowE = 16 * mi + (lane >> 2) + (odd ? 8 : 0);
            uint32_t hp4[4];
            #pragma unroll
            for (int nt = 0; nt < 4; nt++) {
                const float e0 = __shfl_xor_sync(0xffffffffu, acc[mi][nt][0], 1);
                const float e1 = __shfl_xor_sync(0xffffffffu, acc[mi][nt][1], 1);
                const float e2 = __shfl_xor_sync(0xffffffffu, acc[mi][nt][2], 1);
                const float e3 = __shfl_xor_sync(0xffffffffu, acc[mi][nt][3], 1);
                float xi, xf, xg, xo;
                if (!odd) { xi = acc[mi][nt][0]; xf = acc[mi][nt][1]; xg = e0; xo = e1; }
                else      { xi = e2; xf = e3; xg = acc[mi][nt][2]; xo = acc[mi][nt][3]; }
                const int cidx = (2 * p + mi) * 4 + nt;
                const float cn = fmaf(sigf(xf), cst[cidx], sigf(xi) * tanhf_(xg));
                cst[cidx] = cn;
                const float h = sigf(xo) * tanhf_(cn);
                const uint32_t v = (uint32_t)__half_as_ushort(__float2half_rn(h));
                const uint32_t vx = __shfl_xor_sync(0xffffffffu, v, 2);
                hp4[nt] = v | (vx << 16);
            }
            if ((lane & 2) == 0) {
                const uint32_t cuw = ((uint32_t)(4 * p + wn)) ^ (uint32_t)(rowE & 7);
                *(uint4*)(sm + wT + rowE * 256 + (cuw << 4)) =
                    make_uint4(hp4[0], hp4[1], hp4[2], hp4[3]);
            }
        }
    }
}

// ---------------- main kernel ----------------
__global__ void __launch_bounds__(NTH, 3)
lstm_mma_kernel(const float* __restrict__ inseq,
                const float* __restrict__ fcW, const float* __restrict__ fcbp,
                float* __restrict__ out)
{
    extern __shared__ char sm[];
    const uint32_t sA = smem_u32(sm);
    float* tbl  = (float*)(sm + OFF_TBL);
    float* fcw  = (float*)(sm + OFF_FCW);
    float* fcb  = (float*)(sm + OFF_FCB);
    float* xdec = (float*)(sm + OFF_XD);

    const int tid = threadIdx.x;
    const int lane = tid & 31, wn = tid >> 5;   // 4 warps, pure n-split
    const int bm = blockIdx.x * ROWS;
    const int ra = lane >> 2;

    for (int i = tid; i < 256; i += NTH) fcw[i] = fcW[i];
    if (tid < 2) fcb[tid] = fcbp[tid];
    if (tid < 2 * ROWS)
        xdec[tid] = inseq[(size_t)(bm + (tid >> 1)) * 40 + 38 + (tid & 1)];
    for (int i = tid; i < 8192; i += NTH)       // zero all 4 A buffers (32KB)
        ((uint32_t*)sm)[i] = 0u;
    __syncthreads();

    float c0[32], c1[32];
    #pragma unroll
    for (int i = 0; i < 32; i++) { c0[i] = 0.0f; c1[i] = 0.0f; }

    int cur0 = 0, cur1 = 0;
    const int r4[4] = { ra, ra + 8, ra + 16, ra + 24 };   // row slots (mi,half)

    for (int t = 0; t < TTOT; t++) {
        const bool enc = t < TIN;
        if (t == 0 || t == TIN) {
            for (int i = tid; i < 2048; i += NTH) {
                const int seg = i >> 9, idx = i & 511;
                int srcoff;
                if      (seg == 0) srcoff = (enc ? 0 : 1024) + idx;
                else if (seg == 1) srcoff = (enc ? 512 : 1536) + idx;
                else if (seg == 2) srcoff = 2048 + (enc ? 0 : 1024) + idx;
                else               srcoff = 2560 + (enc ? 0 : 1024) + idx;
                tbl[i] = g_tbl[srcoff];
            }
            __syncthreads();
        }
        float xs0[4], xs1[4];
        #pragma unroll
        for (int g = 0; g < 4; g++) {
            if (enc) {
                const float2 xv =
                    *(const float2*)(inseq + (size_t)(bm + r4[g]) * 40 + 2 * t);
                xs0[g] = xv.x; xs1[g] = xv.y;
            } else {
                xs0[g] = xdec[r4[g] * 2];
                xs1[g] = xdec[r4[g] * 2 + 1];
            }
        }
        // ---- layer 0: reads h0[cur0], writes h0[cur0^1] ----
        gemm_layer<128>(sm, sA, (const uint4*)g_wbuf + (enc ? 0 : 8192),
                        tbl, tbl + 1024, tbl + 1536, true, xs0, xs1,
                        c0, lane, wn,
                        AB(0, cur0), AB(0, cur0), AB(0, cur0 ^ 1));
        cur0 ^= 1;
        __syncthreads();   // h0-new visible for L1
        // ---- layer 1: reads [h0 new | h1 old], writes h1[cur1^1] ----
        gemm_layer<256>(sm, sA, (const uint4*)g_wbuf + (enc ? 16384 : 32768),
                        tbl + 512, nullptr, nullptr, false, xs0, xs1,
                        c1, lane, wn,
                        AB(0, cur0), AB(1, cur1), AB(1, cur1 ^ 1));
        cur1 ^= 1;
        __syncthreads();   // h1-new visible
        if (!enc) {
            if (tid < 2 * ROWS) {
                const int r = tid >> 1, o = tid & 1;
                const char* hB = sm + AB(1, cur1) + r * 256;
                float a = fcb[o];
                #pragma unroll 4
                for (int cu = 0; cu < 16; cu++) {
                    const uint32_t dc = ((uint32_t)cu) ^ (uint32_t)(r & 7);
                    const uint4 hq = *(const uint4*)(hB + (dc << 4));
                    const uint32_t hv[4] = {hq.x, hq.y, hq.z, hq.w};
                    #pragma unroll
                    for (int g = 0; g < 4; g++) {
                        a = fmaf(h2lo(hv[g]), fcw[o * 128 + 8 * cu + 2 * g], a);
                        a = fmaf(h2hi(hv[g]), fcw[o * 128 + 8 * cu + 2 * g + 1], a);
                    }
                }
                out[(size_t)(bm + r) * (TDEC * 2) + (t - TIN) * 2 + o] = a;
                xdec[tid] = a;
            }
            __syncthreads();   // xdec visible for next step
        }
    }
}

extern "C" void kernel_launch(void* const* d_in, const int* in_sizes, int n_in,
                              void* d_out, int out_size)
{
    (void)in_sizes; (void)n_in; (void)out_size;
    const float* inseq = (const float*)d_in[0];
    const float* eWih0 = (const float*)d_in[1];
    const float* eWhh0 = (const float*)d_in[2];
    const float* ebih0 = (const float*)d_in[3];
    const float* ebhh0 = (const float*)d_in[4];
    const float* eWih1 = (const float*)d_in[5];
    const float* eWhh1 = (const float*)d_in[6];
    const float* ebih1 = (const float*)d_in[7];
    const float* ebhh1 = (const float*)d_in[8];
    const float* dWih0 = (const float*)d_in[9];
    const float* dWhh0 = (const float*)d_in[10];
    const float* dbih0 = (const float*)d_in[11];
    const float* dbhh0 = (const float*)d_in[12];
    const float* dWih1 = (const float*)d_in[13];
    const float* dWhh1 = (const float*)d_in[14];
    const float* dbih1 = (const float*)d_in[15];
    const float* dbhh1 = (const float*)d_in[16];
    const float* fcW   = (const float*)d_in[17];
    const float* fcb   = (const float*)d_in[18];
    float* out = (float*)d_out;

    prep_weights<<<768, 256>>>(eWhh0, dWhh0, eWih1, eWhh1, dWih1, dWhh1);
    prep_tables<<<16, 256>>>(ebih0, ebhh0, ebih1, ebhh1,
                             dbih0, dbhh0, dbih1, dbhh1, eWih0, dWih0);

    cudaFuncSetAttribute(lstm_mma_kernel,
                         cudaFuncAttributeMaxDynamicSharedMemorySize, SMEM_TOTAL);
    lstm_mma_kernel<<<32768 / ROWS, NTH, SMEM_TOTAL>>>(inseq, fcW, fcb, out);
}